// round 14
// baseline (speedup 1.0000x reference)
#include <cuda_runtime.h>
#include <cuda_bf16.h>
#include <math.h>
#include <stdint.h>

#define BSZ 2
#define TSEQ 2048
#define CDIM 1024
#define NHEAD 16
#define HDIM 64
#define EPS 1e-6f
#define LN2F 0.69314718056f

#define MTOT (BSZ * TSEQ)          // 4096
#define N1 (3 * CDIM)              // 3072
#define KD CDIM                    // 1024

typedef unsigned long long u64;

// ---------------------------------------------------------------------------
// Scratch (__device__ globals; no allocation allowed)
// ---------------------------------------------------------------------------
__device__ __nv_bfloat16 g_xhi[(size_t)MTOT * KD];
__device__ __nv_bfloat16 g_xlo[(size_t)MTOT * KD];
__device__ __nv_bfloat16 g_wqkvT_hi[(size_t)N1 * KD];
__device__ __nv_bfloat16 g_wqkvT_lo[(size_t)N1 * KD];
__device__ __nv_bfloat16 g_woT_hi[(size_t)CDIM * KD];
__device__ __nv_bfloat16 g_woT_lo[(size_t)CDIM * KD];
__device__ __nv_bfloat16 g_atthi[(size_t)MTOT * KD];
__device__ __nv_bfloat16 g_attlo[(size_t)MTOT * KD];

// attention operands: [b*H+h][t][64] bf16 hi/lo + row sq-norms (PRE-SCALED by ln2)
#define BHT ((size_t)BSZ * NHEAD * TSEQ)
__device__ __nv_bfloat16 g_qhi[BHT * HDIM];
__device__ __nv_bfloat16 g_qlo[BHT * HDIM];
__device__ __nv_bfloat16 g_khi[BHT * HDIM];
__device__ __nv_bfloat16 g_klo[BHT * HDIM];
__device__ __nv_bfloat16 g_vhi[BHT * HDIM];
__device__ __nv_bfloat16 g_vlo[BHT * HDIM];
__device__ float g_qsq[BHT];       // |q|^2 * ln2
__device__ float g_ksq[BHT];       // |k|^2 * ln2

// ---------------------------------------------------------------------------
// PTX helpers (baseline sm_80+ / sm_100-family f32x2 — compute_103-safe)
// ---------------------------------------------------------------------------
__device__ __forceinline__ uint32_t smem_u32(const void* p) {
    uint32_t a;
    asm("{ .reg .u64 t; cvta.to.shared.u64 t, %1; cvt.u32.u64 %0, t; }"
        : "=r"(a) : "l"(p));
    return a;
}

#define CP16(dst, src) \
    asm volatile("cp.async.cg.shared.global [%0], [%1], 16;" \
                 :: "r"(dst), "l"(src))
#define CP_COMMIT() asm volatile("cp.async.commit_group;" ::: "memory")
#define CP_WAIT(n)  asm volatile("cp.async.wait_group %0;" :: "n"(n) : "memory")

__device__ __forceinline__ void ldsm_x4(uint32_t* r, uint32_t addr) {
    asm volatile("ldmatrix.sync.aligned.m8n8.x4.shared.b16 {%0,%1,%2,%3}, [%4];"
                 : "=r"(r[0]), "=r"(r[1]), "=r"(r[2]), "=r"(r[3]) : "r"(addr));
}
__device__ __forceinline__ void ldsm_x4t(uint32_t* r, uint32_t addr) {
    asm volatile("ldmatrix.sync.aligned.m8n8.x4.trans.shared.b16 {%0,%1,%2,%3}, [%4];"
                 : "=r"(r[0]), "=r"(r[1]), "=r"(r[2]), "=r"(r[3]) : "r"(addr));
}

__device__ __forceinline__ void mma16816(float* c, const uint32_t* a, const uint32_t* b) {
    asm volatile(
        "mma.sync.aligned.m16n8k16.row.col.f32.bf16.bf16.f32 "
        "{%0,%1,%2,%3}, {%4,%5,%6,%7}, {%8,%9}, {%0,%1,%2,%3};"
        : "+f"(c[0]), "+f"(c[1]), "+f"(c[2]), "+f"(c[3])
        : "r"(a[0]), "r"(a[1]), "r"(a[2]), "r"(a[3]), "r"(b[0]), "r"(b[1]));
}

__device__ __forceinline__ uint32_t pack_bf16x2(float hi, float lo) {
    uint32_t r;
    asm("cvt.rn.bf16x2.f32 %0, %1, %2;" : "=r"(r) : "f"(hi), "f"(lo));
    return r;
}

// ---- packed f32x2 primitives (Blackwell) ----
__device__ __forceinline__ u64 f2pk(float lo, float hi) {
    u64 r; asm("mov.b64 %0, {%1, %2};" : "=l"(r) : "f"(lo), "f"(hi)); return r;
}
__device__ __forceinline__ void f2up(u64 v, float& lo, float& hi) {
    asm("mov.b64 {%0, %1}, %2;" : "=f"(lo), "=f"(hi) : "l"(v));
}
__device__ __forceinline__ u64 f2bcast(float x) { return f2pk(x, x); }
__device__ __forceinline__ u64 f2fma(u64 a, u64 b, u64 c) {
    u64 r; asm("fma.rn.f32x2 %0, %1, %2, %3;" : "=l"(r) : "l"(a), "l"(b), "l"(c)); return r;
}
__device__ __forceinline__ u64 f2mul(u64 a, u64 b) {
    u64 r; asm("mul.rn.f32x2 %0, %1, %2;" : "=l"(r) : "l"(a), "l"(b)); return r;
}
__device__ __forceinline__ u64 f2add(u64 a, u64 b) {
    u64 r; asm("add.rn.f32x2 %0, %1, %2;" : "=l"(r) : "l"(a), "l"(b)); return r;
}

// packed reciprocal: bit trick + 2 Newton (rel err ~1.3e-6, d > 0)
__device__ __forceinline__ u64 f2rcp(u64 d, u64 TWOP, u64 NEG1P) {
    float dl, dh; f2up(d, dl, dh);
    u64 y = f2pk(__uint_as_float(0x7EF311C3u - __float_as_uint(dl)),
                 __uint_as_float(0x7EF311C3u - __float_as_uint(dh)));
    u64 nd = f2mul(d, NEG1P);
    y = f2mul(y, f2fma(nd, y, TWOP));
    y = f2mul(y, f2fma(nd, y, TWOP));
    return y;
}

// packed exp2 (x <= 0): magic round + deg-5 poly; exponent clamp in int domain
__device__ __forceinline__ void f2exp2(u64 x, u64 MAGICP, u64 NEG1P,
                                       u64 PC5, u64 PC4, u64 PC3, u64 PC2, u64 PC1, u64 PC0,
                                       float& r0, float& r1) {
    u64 tt = f2add(x, MAGICP);
    u64 nn = f2fma(MAGICP, NEG1P, tt);  // tt - magic (exact integer)
    u64 ff = f2fma(nn, NEG1P, x);       // x - n  in [-0.5, 0.5]
    u64 p = f2fma(PC5, ff, PC4);
    p = f2fma(p, ff, PC3);
    p = f2fma(p, ff, PC2);
    p = f2fma(p, ff, PC1);
    p = f2fma(p, ff, PC0);
    float tl, th, pl_, ph_;
    f2up(tt, tl, th);
    f2up(p, pl_, ph_);
    int il = max(__float_as_int(tl) - 0x4B400000, -127);
    int ih = max(__float_as_int(th) - 0x4B400000, -127);
    r0 = __int_as_float(__float_as_int(pl_) + (il << 23));
    r1 = __int_as_float(__float_as_int(ph_) + (ih << 23));
}

// scalar exp2 (rescale path only)
__device__ __forceinline__ float exp2_fast(float x) {
    x = fmaxf(x, -126.f);
    float t = x + 12582912.f;
    int   i = __float_as_int(t) - 0x4B400000;
    float f = x - (t - 12582912.f);
    float p =            1.33336498e-3f;
    p = fmaf(p, f, 9.61793571e-3f);
    p = fmaf(p, f, 5.55041087e-2f);
    p = fmaf(p, f, 2.40226507e-1f);
    p = fmaf(p, f, 6.93147182e-1f);
    p = fmaf(p, f, 1.0f);
    return __int_as_float(__float_as_int(p) + (i << 23));
}

// ---------------------------------------------------------------------------
// Pre-pass: split fp32 -> bf16 hi/lo (elementwise)
// ---------------------------------------------------------------------------
__global__ void split_kernel(const float* __restrict__ src,
                             __nv_bfloat16* __restrict__ hi,
                             __nv_bfloat16* __restrict__ lo, int n4) {
    int i = blockIdx.x * blockDim.x + threadIdx.x;
    if (i >= n4) return;
    float4 v = ((const float4*)src)[i];
    float a[4] = {v.x, v.y, v.z, v.w};
    ushort4 hv, lv;
    unsigned short* hp = &hv.x;
    unsigned short* lp = &lv.x;
#pragma unroll
    for (int j = 0; j < 4; j++) {
        __nv_bfloat16 h = __float2bfloat16(a[j]);
        float r = a[j] - __bfloat162float(h);
        __nv_bfloat16 l = __float2bfloat16(r);
        hp[j] = *(unsigned short*)&h;
        lp[j] = *(unsigned short*)&l;
    }
    ((ushort4*)hi)[i] = hv;
    ((ushort4*)lo)[i] = lv;
}

// ---------------------------------------------------------------------------
// Pre-pass: transpose + split  W[K,N] fp32 -> Wt_hi/lo[N,K] bf16 (vectorized)
// ---------------------------------------------------------------------------
__global__ __launch_bounds__(256)
void transpose_split_kernel(const float* __restrict__ W,
                            __nv_bfloat16* __restrict__ hi,
                            __nv_bfloat16* __restrict__ lo, int K, int N) {
    __shared__ float tile[32][33];
    int n0 = blockIdx.x * 32, k0 = blockIdx.y * 32;
    int t = threadIdx.x;
#pragma unroll
    for (int i = 0; i < 4; i++) {
        int idx = t + i * 256;
        int kk = idx >> 5, nn = idx & 31;
        tile[kk][nn] = W[(size_t)(k0 + kk) * N + n0 + nn];
    }
    __syncthreads();
    int n = t >> 3, kg = t & 7;
    ushort4 hv, lv;
    unsigned short* hp = &hv.x;
    unsigned short* lp = &lv.x;
#pragma unroll
    for (int j = 0; j < 4; j++) {
        float v = tile[kg * 4 + j][n];
        __nv_bfloat16 h = __float2bfloat16(v);
        float r = v - __bfloat162float(h);
        __nv_bfloat16 l = __float2bfloat16(r);
        hp[j] = *(unsigned short*)&h;
        lp[j] = *(unsigned short*)&l;
    }
    size_t o = ((size_t)(n0 + n) * K + k0 + kg * 4) >> 2;
    ((ushort4*)hi)[o] = hv;
    ((ushort4*)lo)[o] = lv;
}

// ---------------------------------------------------------------------------
// sq-norm kernel: |row|^2 * ln2 (q and k)
// ---------------------------------------------------------------------------
__global__ __launch_bounds__(256)
void sqnorm_kernel() {
    const uint32_t* hi = blockIdx.y ? (const uint32_t*)g_khi : (const uint32_t*)g_qhi;
    const uint32_t* lo = blockIdx.y ? (const uint32_t*)g_klo : (const uint32_t*)g_qlo;
    float* out = blockIdx.y ? g_ksq : g_qsq;
    size_t gw = (size_t)blockIdx.x * 8 + (threadIdx.x >> 5);
    int lane = threadIdx.x & 31;
    uint32_t h = hi[gw * 32 + lane], l = lo[gw * 32 + lane];
    float f0 = __int_as_float(h << 16) + __int_as_float(l << 16);
    float f1 = __int_as_float(h & 0xFFFF0000u) + __int_as_float(l & 0xFFFF0000u);
    float s = fmaf(f0, f0, f1 * f1);
#pragma unroll
    for (int o = 16; o; o >>= 1) s += __shfl_xor_sync(0xffffffffu, s, o);
    if (lane == 0) out[gw] = s * LN2F;
}

// ---------------------------------------------------------------------------
// HMMA GEMM mainloop (validated): 3-stage cp.async, 1 barrier/k-tile
// ---------------------------------------------------------------------------
#define TILE64 (128 * 64)
#define STG64  (4 * TILE64)
#define GEMM_SMEM (3 * STG64)
#define NKT (KD / 32)

#define SWZ(r, c) ((uint32_t)((r) * 64 + ((((c) + ((r) >> 1)) & 3) << 4)))

__device__ __forceinline__ void g2s_stage(uint32_t sdst,
                                          const __nv_bfloat16* Ah, const __nv_bfloat16* Al,
                                          const __nv_bfloat16* Bh, const __nv_bfloat16* Bl,
                                          int m0, int n0, int k0, int t) {
#pragma unroll
    for (int i = 0; i < 2; i++) {
        int idx = t + i * 256;
        int r = idx >> 2;
        int c = idx & 3;
        uint32_t soff = SWZ(r, c);
        size_t ga = (size_t)(m0 + r) * KD + k0 + c * 8;
        size_t gb = (size_t)(n0 + r) * KD + k0 + c * 8;
        CP16(sdst + soff,              (const char*)(Ah + ga));
        CP16(sdst + TILE64 + soff,     (const char*)(Al + ga));
        CP16(sdst + 2 * TILE64 + soff, (const char*)(Bh + gb));
        CP16(sdst + 3 * TILE64 + soff, (const char*)(Bl + gb));
    }
}

__device__ __forceinline__ void gemm_mainloop(
        uint32_t sb, const __nv_bfloat16* Ah, const __nv_bfloat16* Al,
        const __nv_bfloat16* Bh, const __nv_bfloat16* Bl,
        int m0, int n0, int t, float acc[4][4][4]) {
    const int lane = t & 31;
    const int w    = t >> 5;
    const int wm   = w & 1;
    const int wn   = w >> 1;
    const int g    = lane >> 3;

    uint32_t st0 = sb, st1 = sb + STG64, st2 = sb + 2 * STG64;

    g2s_stage(st0, Ah, Al, Bh, Bl, m0, n0, 0,  t); CP_COMMIT();
    g2s_stage(st1, Ah, Al, Bh, Bl, m0, n0, 32, t); CP_COMMIT();

    for (int kt = 0; kt < NKT; kt++) {
        if (kt == NKT - 1) { CP_WAIT(0); } else { CP_WAIT(1); }
        __syncthreads();
        if (kt + 2 < NKT) {
            g2s_stage(st2, Ah, Al, Bh, Bl, m0, n0, (kt + 2) * 32, t);
            CP_COMMIT();
        }

#pragma unroll
        for (int ks = 0; ks < 2; ks++) {
            uint32_t ah[4][4], al[4][4];
#pragma unroll
            for (int mi = 0; mi < 4; mi++) {
                int row = wm * 64 + mi * 16 + (lane & 15);
                int c   = ks * 2 + (lane >> 4);
                uint32_t ra = st0 + SWZ(row, c);
                ldsm_x4(ah[mi], ra);
                ldsm_x4(al[mi], ra + TILE64);
            }
            uint32_t bh[4][2], bl[4][2];
#pragma unroll
            for (int nb = 0; nb < 2; nb++) {
                int row = wn * 32 + nb * 16 + (g >> 1) * 8 + (lane & 7);
                int c   = ks * 2 + (g & 1);
                uint32_t rb = st0 + 2 * TILE64 + SWZ(row, c);
                ldsm_x4(&bh[2 * nb][0], rb);
                ldsm_x4(&bl[2 * nb][0], rb + TILE64);
            }
#pragma unroll
            for (int mi = 0; mi < 4; mi++)
#pragma unroll
                for (int ni = 0; ni < 4; ni++) mma16816(acc[mi][ni], ah[mi], bh[ni]);
#pragma unroll
            for (int mi = 0; mi < 4; mi++)
#pragma unroll
                for (int ni = 0; ni < 4; ni++) mma16816(acc[mi][ni], ah[mi], bl[ni]);
#pragma unroll
            for (int mi = 0; mi < 4; mi++)
#pragma unroll
                for (int ni = 0; ni < 4; ni++) mma16816(acc[mi][ni], al[mi], bh[ni]);
        }
        uint32_t tmp = st0; st0 = st1; st1 = st2; st2 = tmp;
    }
}

// GEMM2: plain fp32 + bias epilogue (writes final output)
__global__ __launch_bounds__(256, 2)
void mma_gemm_kernel(const __nv_bfloat16* __restrict__ Ah,
                     const __nv_bfloat16* __restrict__ Al,
                     const __nv_bfloat16* __restrict__ Bh,
                     const __nv_bfloat16* __restrict__ Bl,
                     const float* __restrict__ bias,
                     float* __restrict__ C, int N) {
    extern __shared__ char smem[];
    const uint32_t sb = smem_u32(smem);
    const int t = threadIdx.x, lane = t & 31, w = t >> 5;
    const int wm = w & 1, wn = w >> 1;
    const int m0 = blockIdx.y * 128, n0 = blockIdx.x * 128;

    float acc[4][4][4];
#pragma unroll
    for (int mi = 0; mi < 4; mi++)
#pragma unroll
        for (int ni = 0; ni < 4; ni++)
#pragma unroll
            for (int r = 0; r < 4; r++) acc[mi][ni][r] = 0.f;

    gemm_mainloop(sb, Ah, Al, Bh, Bl, m0, n0, t, acc);

#pragma unroll
    for (int mi = 0; mi < 4; mi++) {
        int row = m0 + wm * 64 + mi * 16 + (lane >> 2);
#pragma unroll
        for (int ni = 0; ni < 4; ni++) {
            int col = n0 + wn * 32 + ni * 8 + (lane & 3) * 2;
            float b0 = bias[col], b1 = bias[col + 1];
            float2 v0 = {acc[mi][ni][0] + b0, acc[mi][ni][1] + b1};
            float2 v1 = {acc[mi][ni][2] + b0, acc[mi][ni][3] + b1};
            *(float2*)&C[(size_t)row * N + col]       = v0;
            *(float2*)&C[(size_t)(row + 8) * N + col] = v1;
        }
    }
}

// GEMM1: fused epilogue -> per-head bf16 hi/lo q/k/v
__global__ __launch_bounds__(256, 2)
void mma_gemm_qkv_kernel(const __nv_bfloat16* __restrict__ Ah,
                         const __nv_bfloat16* __restrict__ Al,
                         const __nv_bfloat16* __restrict__ Bh,
                         const __nv_bfloat16* __restrict__ Bl,
                         const float* __restrict__ bias) {
    extern __shared__ char smem[];
    const uint32_t sb = smem_u32(smem);
    const int t = threadIdx.x, lane = t & 31, w = t >> 5;
    const int wm = w & 1, wn = w >> 1;
    const int m0 = blockIdx.y * 128, n0 = blockIdx.x * 128;

    float acc[4][4][4];
#pragma unroll
    for (int mi = 0; mi < 4; mi++)
#pragma unroll
        for (int ni = 0; ni < 4; ni++)
#pragma unroll
            for (int r = 0; r < 4; r++) acc[mi][ni][r] = 0.f;

    gemm_mainloop(sb, Ah, Al, Bh, Bl, m0, n0, t, acc);

    const int sec = n0 >> 10;     // 0=q, 1=k, 2=v
    uint32_t* ph = sec == 0 ? (uint32_t*)g_qhi : sec == 1 ? (uint32_t*)g_khi : (uint32_t*)g_vhi;
    uint32_t* pl = sec == 0 ? (uint32_t*)g_qlo : sec == 1 ? (uint32_t*)g_klo : (uint32_t*)g_vlo;

#pragma unroll
    for (int mi = 0; mi < 4; mi++) {
        int row = m0 + wm * 64 + mi * 16 + (lane >> 2);
        int b   = row >> 11, tok = row & (TSEQ - 1);
#pragma unroll
        for (int ni = 0; ni < 4; ni++) {
            int col  = n0 + wn * 32 + ni * 8 + (lane & 3) * 2;
            int head = (col >> 6) & (NHEAD - 1);
            int d    = col & 63;
            size_t base = ((size_t)(b * NHEAD + head) * TSEQ) * 32 + (d >> 1);
            float b0 = bias[col], b1 = bias[col + 1];
#pragma unroll
            for (int r2 = 0; r2 < 2; r2++) {
                float v0 = acc[mi][ni][2 * r2]     + b0;
                float v1 = acc[mi][ni][2 * r2 + 1] + b1;
                uint32_t hv = pack_bf16x2(v1, v0);
                float r0 = v0 - __int_as_float(hv << 16);
                float r1 = v1 - __int_as_float(hv & 0xFFFF0000u);
                uint32_t lv = pack_bf16x2(r1, r0);
                size_t idx = base + (size_t)(tok + r2 * 8) * 32;
                ph[idx] = hv;
                pl[idx] = lv;
            }
        }
    }
}

// ---------------------------------------------------------------------------
// FlashAttention-style Yat attention.
// 128B swizzled rows, K/V 2-stage rings, ONE barrier per k-tile,
// warp-uniform mask fast path, rescale skip.
// smem: Qhi 0..16K, Qlo 16K..32K, K stages @32768 (stage=16640: Khi,Klo,ksq),
//       V stages @66048 (stage=16384: Vhi,Vlo). total 98816.
// ---------------------------------------------------------------------------
#define SWA(r, c) ((uint32_t)((r) * 128 + ((((c) ^ ((r) & 7)) & 7) << 4)))
#define QLO2  16384u
#define KBASE 32768u
#define KSTG  16640u
#define KSQO  16384u
#define VBASE 66048u
#define VSTG  16384u
#define ATT_SMEM 98816

__device__ __forceinline__ void load_k64(uint32_t dst, const char* kh, const char* kl,
                                         const char* ksq, int kt, int t) {
#pragma unroll
    for (int i = 0; i < 2; i++) {
        int idx = t + i * 256;
        int r = idx >> 3, c = idx & 7;
        uint32_t soff = SWA(r, c);
        size_t gb = (size_t)(kt * 64 + r) * 128 + c * 16;
        CP16(dst + soff,        kh + gb);
        CP16(dst + 8192 + soff, kl + gb);
    }
    if (t < 16) CP16(dst + KSQO + t * 16, ksq + (size_t)kt * 256 + t * 16);
}

__device__ __forceinline__ void load_v64(uint32_t dst, const char* vh, const char* vl,
                                         int kt, int t) {
#pragma unroll
    for (int i = 0; i < 2; i++) {
        int idx = t + i * 256;
        int r = idx >> 3, c = idx & 7;
        uint32_t soff = SWA(r, c);
        size_t gb = (size_t)(kt * 64 + r) * 128 + c * 16;
        CP16(dst + soff,        vh + gb);
        CP16(dst + 8192 + soff, vl + gb);
    }
}

__global__ __launch_bounds__(256, 2)
void yat_attn_mma() {
    extern __shared__ char smem[];
    const uint32_t sb = smem_u32(smem);

    const int t = threadIdx.x, lane = t & 31, w = t >> 5;
    const int h = blockIdx.y, b = blockIdx.z;
    const int qt = gridDim.x - 1 - blockIdx.x;
    const int q0 = qt * 128;
    const int bh = b * NHEAD + h;
    const size_t hb = (size_t)bh * TSEQ * HDIM;

    const char* pQh = (const char*)(g_qhi + hb);
    const char* pQl = (const char*)(g_qlo + hb);
    const char* pKh = (const char*)(g_khi + hb);
    const char* pKl = (const char*)(g_klo + hb);
    const char* pVh = (const char*)(g_vhi + hb);
    const char* pVl = (const char*)(g_vlo + hb);
    const char* pKs = (const char*)(g_ksq + (size_t)bh * TSEQ);

    const int nkt = 2 * qt + 2;

    // prologue: Q + K0 + V0 as one group
#pragma unroll
    for (int i = 0; i < 4; i++) {
        int idx = t + i * 256;
        int r = idx >> 3, c = idx & 7;
        uint32_t s = SWA(r, c);
        size_t gb = (size_t)(q0 + r) * 128 + c * 16;
        CP16(sb + s,        pQh + gb);
        CP16(sb + QLO2 + s, pQl + gb);
    }
    load_k64(sb + KBASE, pKh, pKl, pKs, 0, t);
    load_v64(sb + VBASE, pVh, pVl, 0, t);
    CP_COMMIT();

    const int rl  = lane >> 2;
    const int rg0 = q0 + w * 16 + rl;
    const int rg1 = rg0 + 8;
    const float qa0 = g_qsq[(size_t)bh * TSEQ + rg0] + EPS * LN2F;
    const float qa1 = g_qsq[(size_t)bh * TSEQ + rg1] + EPS * LN2F;

    const u64 MAGICP = f2bcast(12582912.f);
    const u64 NEG1P  = f2bcast(-1.f);
    const u64 TWOP   = f2bcast(2.f);
    const u64 C2P    = f2bcast(-2.f * LN2F);
    const u64 PC5 = f2bcast(1.33336498e-3f);
    const u64 PC4 = f2bcast(9.61793571e-3f);
    const u64 PC3 = f2bcast(5.55041087e-2f);
    const u64 PC2 = f2bcast(2.40226507e-1f);
    const u64 PC1 = f2bcast(6.93147182e-1f);
    const u64 PC0 = f2bcast(1.0f);
    const u64 QA0P = f2bcast(qa0);
    const u64 QA1P = f2bcast(qa1);

    float O[8][4];
#pragma unroll
    for (int dt = 0; dt < 8; dt++)
#pragma unroll
        for (int r = 0; r < 4; r++) O[dt][r] = 0.f;
    float m0 = -1e30f, m1 = -1e30f, l0 = 0.f, l1 = 0.f;

    for (int i = 0; i < nkt; i++) {
        CP_WAIT(0);
        __syncthreads();
        // prefetch next K/V into the stages quiesced by the barrier
        if (i + 1 < nkt) {
            load_k64(sb + KBASE + (uint32_t)((i + 1) & 1) * KSTG, pKh, pKl, pKs, i + 1, t);
            load_v64(sb + VBASE + (uint32_t)((i + 1) & 1) * VSTG, pVh, pVl, i + 1, t);
            CP_COMMIT();
        }

        const uint32_t kst = sb + KBASE + (uint32_t)(i & 1) * KSTG;
        const uint32_t vst = sb + VBASE + (uint32_t)(i & 1) * VSTG;
        const float* ksqp = (const float*)(smem + (kst - sb) + KSQO);
        const int k0 = i * 64;
        const bool need_mask = (k0 + 63 > q0 + w * 16);

        // ---- S = Q K^T (3-way split) ----
        float S[8][4];
#pragma unroll
        for (int nt = 0; nt < 8; nt++)
#pragma unroll
            for (int r = 0; r < 4; r++) S[nt][r] = 0.f;

        const int g = lane >> 3;
#pragma unroll
        for (int ks = 0; ks < 4; ks++) {
            uint32_t ah[4], al[4];
            uint32_t qaddr = sb + SWA(w * 16 + (lane & 15), ks * 2 + (lane >> 4));
            ldsm_x4(ah, qaddr);
            ldsm_x4(al, qaddr + QLO2);
#pragma unroll
            for (int nbp = 0; nbp < 4; nbp += 2) {
                uint32_t bhA[4], blA[4], bhB[4], blB[4];
                int rowA = nbp * 16 + (g >> 1) * 8 + (lane & 7);
                int kc   = ks * 2 + (g & 1);
                uint32_t kaddrA = kst + SWA(rowA, kc);
                uint32_t kaddrB = kaddrA + 2048;     // +16 rows, swizzle invariant
                ldsm_x4(bhA, kaddrA);
                ldsm_x4(blA, kaddrA + 8192);
                ldsm_x4(bhB, kaddrB);
                ldsm_x4(blB, kaddrB + 8192);
                mma16816(S[2 * nbp],     ah, bhA);
                mma16816(S[2 * nbp + 1], ah, bhA + 2);
                mma16816(S[2 * nbp + 2], ah, bhB);
                mma16816(S[2 * nbp + 3], ah, bhB + 2);
                mma16816(S[2 * nbp],     al, bhA);
                mma16816(S[2 * nbp + 1], al, bhA + 2);
                mma16816(S[2 * nbp + 2], al, bhB);
                mma16816(S[2 * nbp + 3], al, bhB + 2);
                mma16816(S[2 * nbp],     ah, blA);
                mma16816(S[2 * nbp + 1], ah, blA + 2);
                mma16816(S[2 * nbp + 2], ah, blB);
                mma16816(S[2 * nbp + 3], ah, blB + 2);
            }
        }

        // ---- scores + mask + max (packed f32x2) ----
        u64 SP[8][2];
        float mx0 = -1e30f, mx1 = -1e30f;
#pragma unroll
        for (int nt = 0; nt < 8; nt++) {
            int cb = nt * 8 + 2 * (lane & 3);
            float2 ksv = *(const float2*)&ksqp[cb];
            u64 kpp = f2pk(ksv.x, ksv.y);
            u64 d0 = f2pk(S[nt][0], S[nt][1]);
            u64 d1 = f2pk(S[nt][2], S[nt][3]);
            u64 den0 = f2fma(C2P, d0, f2add(QA0P, kpp));
            u64 den1 = f2fma(C2P, d1, f2add(QA1P, kpp));
            u64 sl0 = f2mul(f2mul(d0, d0), f2rcp(den0, TWOP, NEG1P));
            u64 sl1 = f2mul(f2mul(d1, d1), f2rcp(den1, TWOP, NEG1P));
            float a0, a1, b0, b1;
            f2up(sl0, a0, a1);
            f2up(sl1, b0, b1);
            if (need_mask) {
                int cg = k0 + cb;
                if (cg > rg0)     a0 = -1e30f;
                if (cg + 1 > rg0) a1 = -1e30f;
                if (cg > rg1)     b0 = -1e30f;
                if (cg + 1 > rg1) b1 = -1e30f;
            }
            mx0 = fmaxf(mx0, fmaxf(a0, a1));
            mx1 = fmaxf(mx1, fmaxf(b0, b1));
            SP[nt][0] = f2pk(a0, a1);
            SP[nt][1] = f2pk(b0, b1);
        }
        mx0 = fmaxf(mx0, __shfl_xor_sync(0xffffffffu, mx0, 1));
        mx0 = fmaxf(mx0, __shfl_xor_sync(0xffffffffu, mx0, 2));
        mx1 = fmaxf(mx1, __shfl_xor_sync(0xffffffffu, mx1, 1));
        mx1 = fmaxf(mx1, __shfl_xor_sync(0xffffffffu, mx1, 2));
        float mn0 = fmaxf(m0, mx0), mn1 = fmaxf(m1, mx1);
        float sc0 = exp2_fast(m0 - mn0), sc1 = exp2_fast(m1 - mn1);
        m0 = mn0; m1 = mn1;
        // rescale only when max actually moved (warp-uniform check)
        if (__any_sync(0xffffffffu, (sc0 != 1.f) || (sc1 != 1.f))) {
            l0 *= sc0; l1 *= sc1;
#pragma unroll
            for (int dt = 0; dt < 8; dt++) {
                O[dt][0] *= sc0; O[dt][1] *= sc0;
                O[dt][2] *= sc1; O[dt][3] *= sc1;
            }
        }

        // ---- p = exp2(sl - m) (packed), split to bf16 hi/lo A-fragments ----
        const u64 NM0 = f2bcast(-mn0);
        const u64 NM1 = f2bcast(-mn1);
        uint32_t pH[8][2], pL[8][2];
#pragma unroll
        for (int nt = 0; nt < 8; nt++) {
            float p0, p1, p2, p3;
            f2exp2(f2add(SP[nt][0], NM0), MAGICP, NEG1P, PC5, PC4, PC3, PC2, PC1, PC0, p0, p1);
            f2exp2(f2add(SP[nt][1], NM1), MAGICP, NEG1P, PC5, PC4, PC3, PC2, PC1, PC0, p2, p3);
            l0 += p0 + p1;
            l1 += p2 + p3;
            uint32_t h0 = pack_bf16x2(p1, p0);
            uint32_t h1 = pack_bf16x2(p3, p2);
            pH[nt][0] = h0; pH[nt][1] = h1;
            float r0 = p0 - __int_as_float(h0 << 16);
            float r1 = p1 - __int_as_float(h0 & 0xFFFF0000u);
            float r2 = p2 - __int_as_float(h1 << 16);
            float r3 = p3 - __int_as_float(h1 & 0xFFFF0000u);
            pL[nt][0] = pack_bf16x2(r1, r0);
            pL[nt][1] = pack_bf16x2(r3, r2);
        }

        // ---- O += P V (3-way split) ----
        const int vrow = (lane & 7) + ((lane >> 3) & 1) * 8;
        const int vc0  = (lane >> 4) & 1;
#pragma unroll
        for (int kc = 0; kc < 4; kc++) {
            uint32_t aH[4] = {pH[2 * kc][0], pH[2 * kc][1], pH[2 * kc + 1][0], pH[2 * kc + 1][1]};
            uint32_t aL[4] = {pL[2 * kc][0], pL[2 * kc][1], pL[2 * kc + 1][0], pL[2 * kc + 1][1]};
            int row = kc * 16 + vrow;
#pragma unroll
            for (int dpp = 0; dpp < 4; dpp += 2) {
                int cA = dpp * 2 + vc0;
                uint32_t vaddrA = vst + SWA(row, cA);
                uint32_t vaddrB = vst + SWA(row, cA + 2);
                uint32_t vhA[4], vlA[4], vhB[4], vlB[4];
                ldsm_x4t(vhA, vaddrA);
                ldsm_x4t(vlA, vaddrA + 8192);
                ldsm_x4t(vhB, vaddrB);
                ldsm_x4t(vlB, vaddrB + 8192);
                mma16816(O[2 * dpp],     aH, vhA);
                mma16816(O[2 * dpp + 1], aH, vhA + 2);
                mma16816(O[2 * dpp + 2], aH, vhB);
                mma16816(O[2 * dpp + 3], aH, vhB + 2);
                mma16816(O[2 * dpp],     aL, vhA);
                mma16816(O[2 * dpp + 1], aL, vhA + 2);
                mma16816(O[2 * dpp + 2], aL, vhB);
                mma16816(O[2 * dpp + 3], aL, vhB + 2);
                mma16816(O[2 * dpp],     aH, vlA);
                mma16816(O[2 * dpp + 1], aH, vlA + 2);
                mma16816(O[2 * dpp + 2], aH, vlB);
                mma16816(O[2 * dpp + 3], aH, vlB + 2);
            }
        }
    }

    // ---- finalize: normalize, split to bf16 hi/lo, store ----
    l0 += __shfl_xor_sync(0xffffffffu, l0, 1);
    l0 += __shfl_xor_sync(0xffffffffu, l0, 2);
    l1 += __shfl_xor_sync(0xffffffffu, l1, 1);
    l1 += __shfl_xor_sync(0xffffffffu, l1, 2);
    float i0 = __fdividef(1.f, l0);
    float i1 = __fdividef(1.f, l1);

    uint32_t* oh = (uint32_t*)g_atthi;
    uint32_t* ol = (uint32_t*)g_attlo;
    size_t base0 = (((size_t)(b * TSEQ + rg0)) * CDIM + h * HDIM + 2 * (lane & 3)) >> 1;
    size_t base1 = (((size_t)(b * TSEQ + rg1)) * CDIM + h * HDIM + 2 * (lane & 3)) >> 1;
#pragma unroll
    for (int dt = 0; dt < 8; dt++) {
        float v0 = O[dt][0] * i0, v1 = O[dt][1] * i0;
        float v2 = O[dt][2] * i1, v3 = O[dt][3] * i1;
        uint32_t h0 = pack_bf16x2(v1, v0);
        uint32_t h1 = pack_bf16x2(v3, v2);
        float r0 = v0 - __int_as_float(h0 << 16);
        float r1 = v1 - __int_as_float(h0 & 0xFFFF0000u);
        float r2 = v2 - __int_as_float(h1 << 16);
        float r3 = v3 - __int_as_float(h1 & 0xFFFF0000u);
        oh[base0 + dt * 4] = h0;
        ol[base0 + dt * 4] = pack_bf16x2(r1, r0);
        oh[base1 + dt * 4] = h1;
        ol[base1 + dt * 4] = pack_bf16x2(r3, r2);
    }
}

// ---------------------------------------------------------------------------
// Launch
// ---------------------------------------------------------------------------
extern "C" void kernel_launch(void* const* d_in, const int* in_sizes, int n_in,
                              void* d_out, int out_size) {
    const float* x     = (const float*)d_in[0];
    const float* w_qkv = (const float*)d_in[1];
    const float* b_qkv = (const float*)d_in[2];
    const float* w_out = (const float*)d_in[3];
    const float* b_out = (const float*)d_in[4];
    float* out = (float*)d_out;

    void *p_xhi, *p_xlo, *p_wqh, *p_wql, *p_woh, *p_wol, *p_ahi, *p_alo;
    cudaGetSymbolAddress(&p_xhi, g_xhi);
    cudaGetSymbolAddress(&p_xlo, g_xlo);
    cudaGetSymbolAddress(&p_wqh, g_wqkvT_hi);
    cudaGetSymbolAddress(&p_wql, g_wqkvT_lo);
    cudaGetSymbolAddress(&p_woh, g_woT_hi);
    cudaGetSymbolAddress(&p_wol, g_woT_lo);
    cudaGetSymbolAddress(&p_ahi, g_atthi);
    cudaGetSymbolAddress(&p_alo, g_attlo);

    static bool attr_done = false;
    if (!attr_done) {
        cudaFuncSetAttribute(mma_gemm_kernel,
                             cudaFuncAttributeMaxDynamicSharedMemorySize, GEMM_SMEM);
        cudaFuncSetAttribute(mma_gemm_qkv_kernel,
                             cudaFuncAttributeMaxDynamicSharedMemorySize, GEMM_SMEM);
        cudaFuncSetAttribute(yat_attn_mma,
                             cudaFuncAttributeMaxDynamicSharedMemorySize, ATT_SMEM);
        attr_done = true;
    }

    // 0) split x, transpose+split weights
    {
        int n4 = MTOT * KD / 4;
        split_kernel<<<(n4 + 255) / 256, 256>>>(x, (__nv_bfloat16*)p_xhi,
                                                (__nv_bfloat16*)p_xlo, n4);
        dim3 g1(N1 / 32, KD / 32);
        transpose_split_kernel<<<g1, 256>>>(w_qkv, (__nv_bfloat16*)p_wqh,
                                            (__nv_bfloat16*)p_wql, KD, N1);
        dim3 g2(CDIM / 32, KD / 32);
        transpose_split_kernel<<<g2, 256>>>(w_out, (__nv_bfloat16*)p_woh,
                                            (__nv_bfloat16*)p_wol, KD, CDIM);
    }

    // 1) QKV projection, fused epilogue -> per-head bf16 splits
    {
        dim3 grid(N1 / 128, MTOT / 128);
        mma_gemm_qkv_kernel<<<grid, 256, GEMM_SMEM>>>(
            (const __nv_bfloat16*)p_xhi, (const __nv_bfloat16*)p_xlo,
            (const __nv_bfloat16*)p_wqh, (const __nv_bfloat16*)p_wql, b_qkv);
    }

    // 2) sq-norms (ln2-scaled) + HMMA flash attention
    {
        dim3 gs((unsigned)(BHT / 8), 2);
        sqnorm_kernel<<<gs, 256>>>();
        dim3 grid(TSEQ / 128, NHEAD, BSZ);
        yat_attn_mma<<<grid, 256, ATT_SMEM>>>();
    }

    // 3) output projection
    {
        dim3 grid(CDIM / 128, MTOT / 128);
        mma_gemm_kernel<<<grid, 256, GEMM_SMEM>>>(
            (const __nv_bfloat16*)p_ahi, (const __nv_bfloat16*)p_alo,
            (const __nv_bfloat16*)p_woh, (const __nv_bfloat16*)p_wol,
            b_out, out, CDIM);
    }
}

// round 15
// speedup vs baseline: 1.5329x; 1.5329x over previous
#include <cuda_runtime.h>
#include <cuda_bf16.h>
#include <math.h>
#include <stdint.h>

#define BSZ 2
#define TSEQ 2048
#define CDIM 1024
#define NHEAD 16
#define HDIM 64
#define EPS 1e-6f
#define LN2F 0.69314718056f

#define MTOT (BSZ * TSEQ)          // 4096
#define N1 (3 * CDIM)              // 3072
#define KD CDIM                    // 1024

typedef unsigned long long u64;

// ---------------------------------------------------------------------------
// Scratch (__device__ globals; no allocation allowed)
// ---------------------------------------------------------------------------
__device__ __nv_bfloat16 g_xhi[(size_t)MTOT * KD];
__device__ __nv_bfloat16 g_xlo[(size_t)MTOT * KD];
__device__ __nv_bfloat16 g_wqkvT_hi[(size_t)N1 * KD];
__device__ __nv_bfloat16 g_wqkvT_lo[(size_t)N1 * KD];
__device__ __nv_bfloat16 g_woT_hi[(size_t)CDIM * KD];
__device__ __nv_bfloat16 g_woT_lo[(size_t)CDIM * KD];
__device__ __nv_bfloat16 g_atthi[(size_t)MTOT * KD];
__device__ __nv_bfloat16 g_attlo[(size_t)MTOT * KD];

// attention operands: [b*H+h][t][64] bf16 hi/lo + row sq-norms (PRE-SCALED by ln2)
#define BHT ((size_t)BSZ * NHEAD * TSEQ)
__device__ __nv_bfloat16 g_qhi[BHT * HDIM];
__device__ __nv_bfloat16 g_qlo[BHT * HDIM];
__device__ __nv_bfloat16 g_khi[BHT * HDIM];
__device__ __nv_bfloat16 g_klo[BHT * HDIM];
__device__ __nv_bfloat16 g_vhi[BHT * HDIM];
__device__ __nv_bfloat16 g_vlo[BHT * HDIM];
__device__ float g_qsq[BHT];       // |q|^2 * ln2
__device__ float g_ksq[BHT];       // |k|^2 * ln2

// ---------------------------------------------------------------------------
// PTX helpers (baseline sm_80+ / sm_100-family f32x2 — compute_103-safe)
// ---------------------------------------------------------------------------
__device__ __forceinline__ uint32_t smem_u32(const void* p) {
    uint32_t a;
    asm("{ .reg .u64 t; cvta.to.shared.u64 t, %1; cvt.u32.u64 %0, t; }"
        : "=r"(a) : "l"(p));
    return a;
}

#define CP16(dst, src) \
    asm volatile("cp.async.cg.shared.global [%0], [%1], 16;" \
                 :: "r"(dst), "l"(src))
#define CP_COMMIT() asm volatile("cp.async.commit_group;" ::: "memory")
#define CP_WAIT(n)  asm volatile("cp.async.wait_group %0;" :: "n"(n) : "memory")

__device__ __forceinline__ void ldsm_x4(uint32_t* r, uint32_t addr) {
    asm volatile("ldmatrix.sync.aligned.m8n8.x4.shared.b16 {%0,%1,%2,%3}, [%4];"
                 : "=r"(r[0]), "=r"(r[1]), "=r"(r[2]), "=r"(r[3]) : "r"(addr));
}
__device__ __forceinline__ void ldsm_x4t(uint32_t* r, uint32_t addr) {
    asm volatile("ldmatrix.sync.aligned.m8n8.x4.trans.shared.b16 {%0,%1,%2,%3}, [%4];"
                 : "=r"(r[0]), "=r"(r[1]), "=r"(r[2]), "=r"(r[3]) : "r"(addr));
}

__device__ __forceinline__ void mma16816(float* c, const uint32_t* a, const uint32_t* b) {
    asm volatile(
        "mma.sync.aligned.m16n8k16.row.col.f32.bf16.bf16.f32 "
        "{%0,%1,%2,%3}, {%4,%5,%6,%7}, {%8,%9}, {%0,%1,%2,%3};"
        : "+f"(c[0]), "+f"(c[1]), "+f"(c[2]), "+f"(c[3])
        : "r"(a[0]), "r"(a[1]), "r"(a[2]), "r"(a[3]), "r"(b[0]), "r"(b[1]));
}

__device__ __forceinline__ uint32_t pack_bf16x2(float hi, float lo) {
    uint32_t r;
    asm("cvt.rn.bf16x2.f32 %0, %1, %2;" : "=r"(r) : "f"(hi), "f"(lo));
    return r;
}

// ---- packed f32x2 primitives (Blackwell) ----
__device__ __forceinline__ u64 f2pk(float lo, float hi) {
    u64 r; asm("mov.b64 %0, {%1, %2};" : "=l"(r) : "f"(lo), "f"(hi)); return r;
}
__device__ __forceinline__ void f2up(u64 v, float& lo, float& hi) {
    asm("mov.b64 {%0, %1}, %2;" : "=f"(lo), "=f"(hi) : "l"(v));
}
__device__ __forceinline__ u64 f2bcast(float x) { return f2pk(x, x); }
__device__ __forceinline__ u64 f2fma(u64 a, u64 b, u64 c) {
    u64 r; asm("fma.rn.f32x2 %0, %1, %2, %3;" : "=l"(r) : "l"(a), "l"(b), "l"(c)); return r;
}
__device__ __forceinline__ u64 f2mul(u64 a, u64 b) {
    u64 r; asm("mul.rn.f32x2 %0, %1, %2;" : "=l"(r) : "l"(a), "l"(b)); return r;
}
__device__ __forceinline__ u64 f2add(u64 a, u64 b) {
    u64 r; asm("add.rn.f32x2 %0, %1, %2;" : "=l"(r) : "l"(a), "l"(b)); return r;
}

// packed reciprocal: bit trick + 2 Newton (rel err ~1.3e-6, d > 0)
__device__ __forceinline__ u64 f2rcp(u64 d, u64 TWOP, u64 NEG1P) {
    float dl, dh; f2up(d, dl, dh);
    u64 y = f2pk(__uint_as_float(0x7EF311C3u - __float_as_uint(dl)),
                 __uint_as_float(0x7EF311C3u - __float_as_uint(dh)));
    u64 nd = f2mul(d, NEG1P);
    y = f2mul(y, f2fma(nd, y, TWOP));
    y = f2mul(y, f2fma(nd, y, TWOP));
    return y;
}

// packed exp2 (x <= 0): magic round + deg-5 poly; exponent clamp in int domain
__device__ __forceinline__ void f2exp2(u64 x, u64 MAGICP, u64 NEG1P,
                                       u64 PC5, u64 PC4, u64 PC3, u64 PC2, u64 PC1, u64 PC0,
                                       float& r0, float& r1) {
    u64 tt = f2add(x, MAGICP);
    u64 nn = f2fma(MAGICP, NEG1P, tt);  // tt - magic (exact integer)
    u64 ff = f2fma(nn, NEG1P, x);       // x - n  in [-0.5, 0.5]
    u64 p = f2fma(PC5, ff, PC4);
    p = f2fma(p, ff, PC3);
    p = f2fma(p, ff, PC2);
    p = f2fma(p, ff, PC1);
    p = f2fma(p, ff, PC0);
    float tl, th, pl_, ph_;
    f2up(tt, tl, th);
    f2up(p, pl_, ph_);
    int il = max(__float_as_int(tl) - 0x4B400000, -127);
    int ih = max(__float_as_int(th) - 0x4B400000, -127);
    r0 = __int_as_float(__float_as_int(pl_) + (il << 23));
    r1 = __int_as_float(__float_as_int(ph_) + (ih << 23));
}

// scalar exp2 (rescale path only)
__device__ __forceinline__ float exp2_fast(float x) {
    x = fmaxf(x, -126.f);
    float t = x + 12582912.f;
    int   i = __float_as_int(t) - 0x4B400000;
    float f = x - (t - 12582912.f);
    float p =            1.33336498e-3f;
    p = fmaf(p, f, 9.61793571e-3f);
    p = fmaf(p, f, 5.55041087e-2f);
    p = fmaf(p, f, 2.40226507e-1f);
    p = fmaf(p, f, 6.93147182e-1f);
    p = fmaf(p, f, 1.0f);
    return __int_as_float(__float_as_int(p) + (i << 23));
}

// ---------------------------------------------------------------------------
// Pre-pass: split fp32 -> bf16 hi/lo (elementwise)
// ---------------------------------------------------------------------------
__global__ void split_kernel(const float* __restrict__ src,
                             __nv_bfloat16* __restrict__ hi,
                             __nv_bfloat16* __restrict__ lo, int n4) {
    int i = blockIdx.x * blockDim.x + threadIdx.x;
    if (i >= n4) return;
    float4 v = ((const float4*)src)[i];
    float a[4] = {v.x, v.y, v.z, v.w};
    ushort4 hv, lv;
    unsigned short* hp = &hv.x;
    unsigned short* lp = &lv.x;
#pragma unroll
    for (int j = 0; j < 4; j++) {
        __nv_bfloat16 h = __float2bfloat16(a[j]);
        float r = a[j] - __bfloat162float(h);
        __nv_bfloat16 l = __float2bfloat16(r);
        hp[j] = *(unsigned short*)&h;
        lp[j] = *(unsigned short*)&l;
    }
    ((ushort4*)hi)[i] = hv;
    ((ushort4*)lo)[i] = lv;
}

// ---------------------------------------------------------------------------
// Pre-pass: transpose + split  W[K,N] fp32 -> Wt_hi/lo[N,K] bf16 (vectorized)
// ---------------------------------------------------------------------------
__global__ __launch_bounds__(256)
void transpose_split_kernel(const float* __restrict__ W,
                            __nv_bfloat16* __restrict__ hi,
                            __nv_bfloat16* __restrict__ lo, int K, int N) {
    __shared__ float tile[32][33];
    int n0 = blockIdx.x * 32, k0 = blockIdx.y * 32;
    int t = threadIdx.x;
#pragma unroll
    for (int i = 0; i < 4; i++) {
        int idx = t + i * 256;
        int kk = idx >> 5, nn = idx & 31;
        tile[kk][nn] = W[(size_t)(k0 + kk) * N + n0 + nn];
    }
    __syncthreads();
    int n = t >> 3, kg = t & 7;
    ushort4 hv, lv;
    unsigned short* hp = &hv.x;
    unsigned short* lp = &lv.x;
#pragma unroll
    for (int j = 0; j < 4; j++) {
        float v = tile[kg * 4 + j][n];
        __nv_bfloat16 h = __float2bfloat16(v);
        float r = v - __bfloat162float(h);
        __nv_bfloat16 l = __float2bfloat16(r);
        hp[j] = *(unsigned short*)&h;
        lp[j] = *(unsigned short*)&l;
    }
    size_t o = ((size_t)(n0 + n) * K + k0 + kg * 4) >> 2;
    ((ushort4*)hi)[o] = hv;
    ((ushort4*)lo)[o] = lv;
}

// ---------------------------------------------------------------------------
// sq-norm kernel: |row|^2 * ln2 (q and k)
// ---------------------------------------------------------------------------
__global__ __launch_bounds__(256)
void sqnorm_kernel() {
    const uint32_t* hi = blockIdx.y ? (const uint32_t*)g_khi : (const uint32_t*)g_qhi;
    const uint32_t* lo = blockIdx.y ? (const uint32_t*)g_klo : (const uint32_t*)g_qlo;
    float* out = blockIdx.y ? g_ksq : g_qsq;
    size_t gw = (size_t)blockIdx.x * 8 + (threadIdx.x >> 5);
    int lane = threadIdx.x & 31;
    uint32_t h = hi[gw * 32 + lane], l = lo[gw * 32 + lane];
    float f0 = __int_as_float(h << 16) + __int_as_float(l << 16);
    float f1 = __int_as_float(h & 0xFFFF0000u) + __int_as_float(l & 0xFFFF0000u);
    float s = fmaf(f0, f0, f1 * f1);
#pragma unroll
    for (int o = 16; o; o >>= 1) s += __shfl_xor_sync(0xffffffffu, s, o);
    if (lane == 0) out[gw] = s * LN2F;
}

// ---------------------------------------------------------------------------
// HMMA GEMM mainloop (validated): 3-stage cp.async, 1 barrier/k-tile
// ---------------------------------------------------------------------------
#define TILE64 (128 * 64)
#define STG64  (4 * TILE64)
#define GEMM_SMEM (3 * STG64)
#define NKT (KD / 32)

#define SWZ(r, c) ((uint32_t)((r) * 64 + ((((c) + ((r) >> 1)) & 3) << 4)))

__device__ __forceinline__ void g2s_stage(uint32_t sdst,
                                          const __nv_bfloat16* Ah, const __nv_bfloat16* Al,
                                          const __nv_bfloat16* Bh, const __nv_bfloat16* Bl,
                                          int m0, int n0, int k0, int t) {
#pragma unroll
    for (int i = 0; i < 2; i++) {
        int idx = t + i * 256;
        int r = idx >> 2;
        int c = idx & 3;
        uint32_t soff = SWZ(r, c);
        size_t ga = (size_t)(m0 + r) * KD + k0 + c * 8;
        size_t gb = (size_t)(n0 + r) * KD + k0 + c * 8;
        CP16(sdst + soff,              (const char*)(Ah + ga));
        CP16(sdst + TILE64 + soff,     (const char*)(Al + ga));
        CP16(sdst + 2 * TILE64 + soff, (const char*)(Bh + gb));
        CP16(sdst + 3 * TILE64 + soff, (const char*)(Bl + gb));
    }
}

__device__ __forceinline__ void gemm_mainloop(
        uint32_t sb, const __nv_bfloat16* Ah, const __nv_bfloat16* Al,
        const __nv_bfloat16* Bh, const __nv_bfloat16* Bl,
        int m0, int n0, int t, float acc[4][4][4]) {
    const int lane = t & 31;
    const int w    = t >> 5;
    const int wm   = w & 1;
    const int wn   = w >> 1;
    const int g    = lane >> 3;

    uint32_t st0 = sb, st1 = sb + STG64, st2 = sb + 2 * STG64;

    g2s_stage(st0, Ah, Al, Bh, Bl, m0, n0, 0,  t); CP_COMMIT();
    g2s_stage(st1, Ah, Al, Bh, Bl, m0, n0, 32, t); CP_COMMIT();

    for (int kt = 0; kt < NKT; kt++) {
        if (kt == NKT - 1) { CP_WAIT(0); } else { CP_WAIT(1); }
        __syncthreads();
        if (kt + 2 < NKT) {
            g2s_stage(st2, Ah, Al, Bh, Bl, m0, n0, (kt + 2) * 32, t);
            CP_COMMIT();
        }

#pragma unroll
        for (int ks = 0; ks < 2; ks++) {
            uint32_t ah[4][4], al[4][4];
#pragma unroll
            for (int mi = 0; mi < 4; mi++) {
                int row = wm * 64 + mi * 16 + (lane & 15);
                int c   = ks * 2 + (lane >> 4);
                uint32_t ra = st0 + SWZ(row, c);
                ldsm_x4(ah[mi], ra);
                ldsm_x4(al[mi], ra + TILE64);
            }
            uint32_t bh[4][2], bl[4][2];
#pragma unroll
            for (int nb = 0; nb < 2; nb++) {
                int row = wn * 32 + nb * 16 + (g >> 1) * 8 + (lane & 7);
                int c   = ks * 2 + (g & 1);
                uint32_t rb = st0 + 2 * TILE64 + SWZ(row, c);
                ldsm_x4(&bh[2 * nb][0], rb);
                ldsm_x4(&bl[2 * nb][0], rb + TILE64);
            }
#pragma unroll
            for (int mi = 0; mi < 4; mi++)
#pragma unroll
                for (int ni = 0; ni < 4; ni++) mma16816(acc[mi][ni], ah[mi], bh[ni]);
#pragma unroll
            for (int mi = 0; mi < 4; mi++)
#pragma unroll
                for (int ni = 0; ni < 4; ni++) mma16816(acc[mi][ni], ah[mi], bl[ni]);
#pragma unroll
            for (int mi = 0; mi < 4; mi++)
#pragma unroll
                for (int ni = 0; ni < 4; ni++) mma16816(acc[mi][ni], al[mi], bh[ni]);
        }
        uint32_t tmp = st0; st0 = st1; st1 = st2; st2 = tmp;
    }
}

// GEMM2: plain fp32 + bias epilogue (writes final output)
__global__ __launch_bounds__(256, 2)
void mma_gemm_kernel(const __nv_bfloat16* __restrict__ Ah,
                     const __nv_bfloat16* __restrict__ Al,
                     const __nv_bfloat16* __restrict__ Bh,
                     const __nv_bfloat16* __restrict__ Bl,
                     const float* __restrict__ bias,
                     float* __restrict__ C, int N) {
    extern __shared__ char smem[];
    const uint32_t sb = smem_u32(smem);
    const int t = threadIdx.x, lane = t & 31, w = t >> 5;
    const int wm = w & 1, wn = w >> 1;
    const int m0 = blockIdx.y * 128, n0 = blockIdx.x * 128;

    float acc[4][4][4];
#pragma unroll
    for (int mi = 0; mi < 4; mi++)
#pragma unroll
        for (int ni = 0; ni < 4; ni++)
#pragma unroll
            for (int r = 0; r < 4; r++) acc[mi][ni][r] = 0.f;

    gemm_mainloop(sb, Ah, Al, Bh, Bl, m0, n0, t, acc);

#pragma unroll
    for (int mi = 0; mi < 4; mi++) {
        int row = m0 + wm * 64 + mi * 16 + (lane >> 2);
#pragma unroll
        for (int ni = 0; ni < 4; ni++) {
            int col = n0 + wn * 32 + ni * 8 + (lane & 3) * 2;
            float b0 = bias[col], b1 = bias[col + 1];
            float2 v0 = {acc[mi][ni][0] + b0, acc[mi][ni][1] + b1};
            float2 v1 = {acc[mi][ni][2] + b0, acc[mi][ni][3] + b1};
            *(float2*)&C[(size_t)row * N + col]       = v0;
            *(float2*)&C[(size_t)(row + 8) * N + col] = v1;
        }
    }
}

// GEMM1: fused epilogue -> per-head bf16 hi/lo q/k/v
__global__ __launch_bounds__(256, 2)
void mma_gemm_qkv_kernel(const __nv_bfloat16* __restrict__ Ah,
                         const __nv_bfloat16* __restrict__ Al,
                         const __nv_bfloat16* __restrict__ Bh,
                         const __nv_bfloat16* __restrict__ Bl,
                         const float* __restrict__ bias) {
    extern __shared__ char smem[];
    const uint32_t sb = smem_u32(smem);
    const int t = threadIdx.x, lane = t & 31, w = t >> 5;
    const int wm = w & 1, wn = w >> 1;
    const int m0 = blockIdx.y * 128, n0 = blockIdx.x * 128;

    float acc[4][4][4];
#pragma unroll
    for (int mi = 0; mi < 4; mi++)
#pragma unroll
        for (int ni = 0; ni < 4; ni++)
#pragma unroll
            for (int r = 0; r < 4; r++) acc[mi][ni][r] = 0.f;

    gemm_mainloop(sb, Ah, Al, Bh, Bl, m0, n0, t, acc);

    const int sec = n0 >> 10;     // 0=q, 1=k, 2=v
    uint32_t* ph = sec == 0 ? (uint32_t*)g_qhi : sec == 1 ? (uint32_t*)g_khi : (uint32_t*)g_vhi;
    uint32_t* pl = sec == 0 ? (uint32_t*)g_qlo : sec == 1 ? (uint32_t*)g_klo : (uint32_t*)g_vlo;

#pragma unroll
    for (int mi = 0; mi < 4; mi++) {
        int row = m0 + wm * 64 + mi * 16 + (lane >> 2);
        int b   = row >> 11, tok = row & (TSEQ - 1);
#pragma unroll
        for (int ni = 0; ni < 4; ni++) {
            int col  = n0 + wn * 32 + ni * 8 + (lane & 3) * 2;
            int head = (col >> 6) & (NHEAD - 1);
            int d    = col & 63;
            size_t base = ((size_t)(b * NHEAD + head) * TSEQ) * 32 + (d >> 1);
            float b0 = bias[col], b1 = bias[col + 1];
#pragma unroll
            for (int r2 = 0; r2 < 2; r2++) {
                float v0 = acc[mi][ni][2 * r2]     + b0;
                float v1 = acc[mi][ni][2 * r2 + 1] + b1;
                uint32_t hv = pack_bf16x2(v1, v0);
                float r0 = v0 - __int_as_float(hv << 16);
                float r1 = v1 - __int_as_float(hv & 0xFFFF0000u);
                uint32_t lv = pack_bf16x2(r1, r0);
                size_t idx = base + (size_t)(tok + r2 * 8) * 32;
                ph[idx] = hv;
                pl[idx] = lv;
            }
        }
    }
}

// ---------------------------------------------------------------------------
// FlashAttention-style Yat attention (round-12 structure: 144B rows, 2-stage
// 2-deep prefetch, two barriers/tile) + mask fast path + rescale skip.
// ---------------------------------------------------------------------------
#define AROWB 144
#define QLOFF  18432
#define SBASE  36864
#define KLOFF  9216
#define VHOFF  18432
#define VLOFF  27648
#define KSQOFF 36864
#define ASTG   37120
#define ATT_SMEM (SBASE + 2 * ASTG)

__device__ __forceinline__ void load_kv(uint32_t dst,
                                        const char* kh, const char* kl,
                                        const char* vh, const char* vl,
                                        const char* ksq, int kt, int t) {
#pragma unroll
    for (int i = 0; i < 2; i++) {
        int idx = t + i * 256;
        int rr = idx >> 3, cc = idx & 7;
        uint32_t off = (uint32_t)(rr * AROWB + cc * 16);
        size_t gbyte = ((size_t)(kt * 64 + rr) * HDIM + cc * 8) * 2;
        CP16(dst + off,         kh + gbyte);
        CP16(dst + KLOFF + off, kl + gbyte);
        CP16(dst + VHOFF + off, vh + gbyte);
        CP16(dst + VLOFF + off, vl + gbyte);
    }
    if (t < 16) CP16(dst + KSQOFF + t * 16, ksq + (size_t)kt * 64 * 4 + t * 16);
}

__global__ __launch_bounds__(256, 2)
void yat_attn_mma() {
    extern __shared__ char smem[];
    const uint32_t sb = smem_u32(smem);

    const int t = threadIdx.x, lane = t & 31, w = t >> 5;
    const int h = blockIdx.y, b = blockIdx.z;
    const int qt = gridDim.x - 1 - blockIdx.x;
    const int q0 = qt * 128;
    const int bh = b * NHEAD + h;
    const size_t hb = (size_t)bh * TSEQ * HDIM;

    const char* pQh = (const char*)(g_qhi + hb);
    const char* pQl = (const char*)(g_qlo + hb);
    const char* pKh = (const char*)(g_khi + hb);
    const char* pKl = (const char*)(g_klo + hb);
    const char* pVh = (const char*)(g_vhi + hb);
    const char* pVl = (const char*)(g_vlo + hb);
    const char* pKs = (const char*)(g_ksq + (size_t)bh * TSEQ);

    const int nkt = 2 * qt + 2;

#pragma unroll
    for (int i = 0; i < 4; i++) {
        int idx = t + i * 256;
        int r = idx >> 3, c = idx & 7;
        uint32_t d = sb + (uint32_t)(r * AROWB + c * 16);
        size_t gbyte = ((size_t)(q0 + r) * HDIM + c * 8) * 2;
        CP16(d,          pQh + gbyte);
        CP16(d + QLOFF,  pQl + gbyte);
    }
    CP_COMMIT();
    load_kv(sb + SBASE,        pKh, pKl, pVh, pVl, pKs, 0, t); CP_COMMIT();
    load_kv(sb + SBASE + ASTG, pKh, pKl, pVh, pVl, pKs, 1, t); CP_COMMIT();

    const int rl  = lane >> 2;
    const int rg0 = q0 + w * 16 + rl;
    const int rg1 = rg0 + 8;
    const float qa0 = g_qsq[(size_t)bh * TSEQ + rg0] + EPS * LN2F;
    const float qa1 = g_qsq[(size_t)bh * TSEQ + rg1] + EPS * LN2F;

    const u64 MAGICP = f2bcast(12582912.f);
    const u64 NEG1P  = f2bcast(-1.f);
    const u64 TWOP   = f2bcast(2.f);
    const u64 C2P    = f2bcast(-2.f * LN2F);
    const u64 PC5 = f2bcast(1.33336498e-3f);
    const u64 PC4 = f2bcast(9.61793571e-3f);
    const u64 PC3 = f2bcast(5.55041087e-2f);
    const u64 PC2 = f2bcast(2.40226507e-1f);
    const u64 PC1 = f2bcast(6.93147182e-1f);
    const u64 PC0 = f2bcast(1.0f);
    const u64 QA0P = f2bcast(qa0);
    const u64 QA1P = f2bcast(qa1);

    float O[8][4];
#pragma unroll
    for (int dt = 0; dt < 8; dt++)
#pragma unroll
        for (int r = 0; r < 4; r++) O[dt][r] = 0.f;
    float m0 = -1e30f, m1 = -1e30f, l0 = 0.f, l1 = 0.f;

    for (int i = 0; i < nkt; i++) {
        if (i == nkt - 1) { CP_WAIT(0); } else { CP_WAIT(1); }
        __syncthreads();

        const uint32_t kb = sb + SBASE + (uint32_t)(i & 1) * ASTG;
        const char* kbp = smem + SBASE + (size_t)(i & 1) * ASTG;
        const float* ksqp = (const float*)(kbp + KSQOFF);
        const int k0 = i * 64;
        const bool need_mask = (k0 + 63 > q0 + w * 16);

        // ---- S = Q K^T (3-way split) ----
        float S[8][4];
#pragma unroll
        for (int nt = 0; nt < 8; nt++)
#pragma unroll
            for (int r = 0; r < 4; r++) S[nt][r] = 0.f;

        const int g = lane >> 3;
#pragma unroll
        for (int ks = 0; ks < 4; ks++) {
            uint32_t ah[4], al[4];
            uint32_t qaddr = sb + (uint32_t)((w * 16 + (lane & 15)) * AROWB
                                             + ks * 32 + (lane >> 4) * 16);
            ldsm_x4(ah, qaddr);
            ldsm_x4(al, qaddr + QLOFF);
#pragma unroll
            for (int nbp = 0; nbp < 4; nbp += 2) {
                uint32_t bhA[4], blA[4], bhB[4], blB[4];
                uint32_t kaddrA = kb + (uint32_t)((nbp * 16 + (g >> 1) * 8 + (lane & 7)) * AROWB
                                                  + ks * 32 + (g & 1) * 16);
                uint32_t kaddrB = kaddrA + 16 * AROWB;
                ldsm_x4(bhA, kaddrA);
                ldsm_x4(blA, kaddrA + KLOFF);
                ldsm_x4(bhB, kaddrB);
                ldsm_x4(blB, kaddrB + KLOFF);
                mma16816(S[2 * nbp],     ah, bhA);
                mma16816(S[2 * nbp + 1], ah, bhA + 2);
                mma16816(S[2 * nbp + 2], ah, bhB);
                mma16816(S[2 * nbp + 3], ah, bhB + 2);
                mma16816(S[2 * nbp],     al, bhA);
                mma16816(S[2 * nbp + 1], al, bhA + 2);
                mma16816(S[2 * nbp + 2], al, bhB);
                mma16816(S[2 * nbp + 3], al, bhB + 2);
                mma16816(S[2 * nbp],     ah, blA);
                mma16816(S[2 * nbp + 1], ah, blA + 2);
                mma16816(S[2 * nbp + 2], ah, blB);
                mma16816(S[2 * nbp + 3], ah, blB + 2);
            }
        }

        // ---- scores + mask + max (packed f32x2) ----
        u64 SP[8][2];
        float mx0 = -1e30f, mx1 = -1e30f;
#pragma unroll
        for (int nt = 0; nt < 8; nt++) {
            int cb = nt * 8 + 2 * (lane & 3);
            float2 ksv = *(const float2*)&ksqp[cb];
            u64 kpp = f2pk(ksv.x, ksv.y);
            u64 d0 = f2pk(S[nt][0], S[nt][1]);
            u64 d1 = f2pk(S[nt][2], S[nt][3]);
            u64 den0 = f2fma(C2P, d0, f2add(QA0P, kpp));
            u64 den1 = f2fma(C2P, d1, f2add(QA1P, kpp));
            u64 sl0 = f2mul(f2mul(d0, d0), f2rcp(den0, TWOP, NEG1P));
            u64 sl1 = f2mul(f2mul(d1, d1), f2rcp(den1, TWOP, NEG1P));
            float a0, a1, b0, b1;
            f2up(sl0, a0, a1);
            f2up(sl1, b0, b1);
            if (need_mask) {
                int cg = k0 + cb;
                if (cg > rg0)     a0 = -1e30f;
                if (cg + 1 > rg0) a1 = -1e30f;
                if (cg > rg1)     b0 = -1e30f;
                if (cg + 1 > rg1) b1 = -1e30f;
            }
            mx0 = fmaxf(mx0, fmaxf(a0, a1));
            mx1 = fmaxf(mx1, fmaxf(b0, b1));
            SP[nt][0] = f2pk(a0, a1);
            SP[nt][1] = f2pk(b0, b1);
        }
        mx0 = fmaxf(mx0, __shfl_xor_sync(0xffffffffu, mx0, 1));
        mx0 = fmaxf(mx0, __shfl_xor_sync(0xffffffffu, mx0, 2));
        mx1 = fmaxf(mx1, __shfl_xor_sync(0xffffffffu, mx1, 1));
        mx1 = fmaxf(mx1, __shfl_xor_sync(0xffffffffu, mx1, 2));
        float mn0 = fmaxf(m0, mx0), mn1 = fmaxf(m1, mx1);
        float sc0 = exp2_fast(m0 - mn0), sc1 = exp2_fast(m1 - mn1);
        m0 = mn0; m1 = mn1;
        if (__any_sync(0xffffffffu, (sc0 != 1.f) || (sc1 != 1.f))) {
            l0 *= sc0; l1 *= sc1;
#pragma unroll
            for (int dt = 0; dt < 8; dt++) {
                O[dt][0] *= sc0; O[dt][1] *= sc0;
                O[dt][2] *= sc1; O[dt][3] *= sc1;
            }
        }

        // ---- p = exp2(sl - m) (packed), split to bf16 hi/lo A-fragments ----
        const u64 NM0 = f2bcast(-mn0);
        const u64 NM1 = f2bcast(-mn1);
        uint32_t pH[8][2], pL[8][2];
#pragma unroll
        for (int nt = 0; nt < 8; nt++) {
            float p0, p1, p2, p3;
            f2exp2(f2add(SP[nt][0], NM0), MAGICP, NEG1P, PC5, PC4, PC3, PC2, PC1, PC0, p0, p1);
            f2exp2(f2add(SP[nt][1], NM1), MAGICP, NEG1P, PC5, PC4, PC3, PC2, PC1, PC0, p2, p3);
            l0 += p0 + p1;
            l1 += p2 + p3;
            uint32_t h0 = pack_bf16x2(p1, p0);
            uint32_t h1 = pack_bf16x2(p3, p2);
            pH[nt][0] = h0; pH[nt][1] = h1;
            float r0 = p0 - __int_as_float(h0 << 16);
            float r1 = p1 - __int_as_float(h0 & 0xFFFF0000u);
            float r2 = p2 - __int_as_float(h1 << 16);
            float r3 = p3 - __int_as_float(h1 & 0xFFFF0000u);
            pL[nt][0] = pack_bf16x2(r1, r0);
            pL[nt][1] = pack_bf16x2(r3, r2);
        }

        // ---- O += P V (3-way split) ----
        const int vrow = (lane & 7) + ((lane >> 3) & 1) * 8;
        const int vcol = ((lane >> 4) & 1) * 16;
#pragma unroll
        for (int kc = 0; kc < 4; kc++) {
            uint32_t aH[4] = {pH[2 * kc][0], pH[2 * kc][1], pH[2 * kc + 1][0], pH[2 * kc + 1][1]};
            uint32_t aL[4] = {pL[2 * kc][0], pL[2 * kc][1], pL[2 * kc + 1][0], pL[2 * kc + 1][1]};
#pragma unroll
            for (int dpp = 0; dpp < 4; dpp += 2) {
                uint32_t vaddrA = kb + VHOFF
                                + (uint32_t)((kc * 16 + vrow) * AROWB + dpp * 32 + vcol);
                uint32_t vaddrB = vaddrA + 32;
                uint32_t vhA[4], vlA[4], vhB[4], vlB[4];
                ldsm_x4t(vhA, vaddrA);
                ldsm_x4t(vlA, vaddrA + KLOFF);
                ldsm_x4t(vhB, vaddrB);
                ldsm_x4t(vlB, vaddrB + KLOFF);
                mma16816(O[2 * dpp],     aH, vhA);
                mma16816(O[2 * dpp + 1], aH, vhA + 2);
                mma16816(O[2 * dpp + 2], aH, vhB);
                mma16816(O[2 * dpp + 3], aH, vhB + 2);
                mma16816(O[2 * dpp],     aL, vhA);
                mma16816(O[2 * dpp + 1], aL, vhA + 2);
                mma16816(O[2 * dpp + 2], aL, vhB);
                mma16816(O[2 * dpp + 3], aL, vhB + 2);
                mma16816(O[2 * dpp],     aH, vlA);
                mma16816(O[2 * dpp + 1], aH, vlA + 2);
                mma16816(O[2 * dpp + 2], aH, vlB);
                mma16816(O[2 * dpp + 3], aH, vlB + 2);
            }
        }

        __syncthreads();
        if (i + 2 < nkt) {
            load_kv(kb, pKh, pKl, pVh, pVl, pKs, i + 2, t);
            CP_COMMIT();
        }
    }

    // ---- finalize: normalize, split to bf16 hi/lo, store ----
    l0 += __shfl_xor_sync(0xffffffffu, l0, 1);
    l0 += __shfl_xor_sync(0xffffffffu, l0, 2);
    l1 += __shfl_xor_sync(0xffffffffu, l1, 1);
    l1 += __shfl_xor_sync(0xffffffffu, l1, 2);
    float i0 = __fdividef(1.f, l0);
    float i1 = __fdividef(1.f, l1);

    uint32_t* oh = (uint32_t*)g_atthi;
    uint32_t* ol = (uint32_t*)g_attlo;
    size_t base0 = (((size_t)(b * TSEQ + rg0)) * CDIM + h * HDIM + 2 * (lane & 3)) >> 1;
    size_t base1 = (((size_t)(b * TSEQ + rg1)) * CDIM + h * HDIM + 2 * (lane & 3)) >> 1;
#pragma unroll
    for (int dt = 0; dt < 8; dt++) {
        float v0 = O[dt][0] * i0, v1 = O[dt][1] * i0;
        float v2 = O[dt][2] * i1, v3 = O[dt][3] * i1;
        uint32_t h0 = pack_bf16x2(v1, v0);
        uint32_t h1 = pack_bf16x2(v3, v2);
        float r0 = v0 - __int_as_float(h0 << 16);
        float r1 = v1 - __int_as_float(h0 & 0xFFFF0000u);
        float r2 = v2 - __int_as_float(h1 << 16);
        float r3 = v3 - __int_as_float(h1 & 0xFFFF0000u);
        oh[base0 + dt * 4] = h0;
        ol[base0 + dt * 4] = pack_bf16x2(r1, r0);
        oh[base1 + dt * 4] = h1;
        ol[base1 + dt * 4] = pack_bf16x2(r3, r2);
    }
}

// ---------------------------------------------------------------------------
// Launch
// ---------------------------------------------------------------------------
extern "C" void kernel_launch(void* const* d_in, const int* in_sizes, int n_in,
                              void* d_out, int out_size) {
    const float* x     = (const float*)d_in[0];
    const float* w_qkv = (const float*)d_in[1];
    const float* b_qkv = (const float*)d_in[2];
    const float* w_out = (const float*)d_in[3];
    const float* b_out = (const float*)d_in[4];
    float* out = (float*)d_out;

    void *p_xhi, *p_xlo, *p_wqh, *p_wql, *p_woh, *p_wol, *p_ahi, *p_alo;
    cudaGetSymbolAddress(&p_xhi, g_xhi);
    cudaGetSymbolAddress(&p_xlo, g_xlo);
    cudaGetSymbolAddress(&p_wqh, g_wqkvT_hi);
    cudaGetSymbolAddress(&p_wql, g_wqkvT_lo);
    cudaGetSymbolAddress(&p_woh, g_woT_hi);
    cudaGetSymbolAddress(&p_wol, g_woT_lo);
    cudaGetSymbolAddress(&p_ahi, g_atthi);
    cudaGetSymbolAddress(&p_alo, g_attlo);

    static bool attr_done = false;
    if (!attr_done) {
        cudaFuncSetAttribute(mma_gemm_kernel,
                             cudaFuncAttributeMaxDynamicSharedMemorySize, GEMM_SMEM);
        cudaFuncSetAttribute(mma_gemm_qkv_kernel,
                             cudaFuncAttributeMaxDynamicSharedMemorySize, GEMM_SMEM);
        cudaFuncSetAttribute(yat_attn_mma,
                             cudaFuncAttributeMaxDynamicSharedMemorySize, ATT_SMEM);
        attr_done = true;
    }

    // 0) split x, transpose+split weights
    {
        int n4 = MTOT * KD / 4;
        split_kernel<<<(n4 + 255) / 256, 256>>>(x, (__nv_bfloat16*)p_xhi,
                                                (__nv_bfloat16*)p_xlo, n4);
        dim3 g1(N1 / 32, KD / 32);
        transpose_split_kernel<<<g1, 256>>>(w_qkv, (__nv_bfloat16*)p_wqh,
                                            (__nv_bfloat16*)p_wql, KD, N1);
        dim3 g2(CDIM / 32, KD / 32);
        transpose_split_kernel<<<g2, 256>>>(w_out, (__nv_bfloat16*)p_woh,
                                            (__nv_bfloat16*)p_wol, KD, CDIM);
    }

    // 1) QKV projection, fused epilogue -> per-head bf16 splits
    {
        dim3 grid(N1 / 128, MTOT / 128);
        mma_gemm_qkv_kernel<<<grid, 256, GEMM_SMEM>>>(
            (const __nv_bfloat16*)p_xhi, (const __nv_bfloat16*)p_xlo,
            (const __nv_bfloat16*)p_wqh, (const __nv_bfloat16*)p_wql, b_qkv);
    }

    // 2) sq-norms (ln2-scaled) + HMMA flash attention
    {
        dim3 gs((unsigned)(BHT / 8), 2);
        sqnorm_kernel<<<gs, 256>>>();
        dim3 grid(TSEQ / 128, NHEAD, BSZ);
        yat_attn_mma<<<grid, 256, ATT_SMEM>>>();
    }

    // 3) output projection
    {
        dim3 grid(CDIM / 128, MTOT / 128);
        mma_gemm_kernel<<<grid, 256, GEMM_SMEM>>>(
            (const __nv_bfloat16*)p_ahi, (const __nv_bfloat16*)p_alo,
            (const __nv_bfloat16*)p_woh, (const __nv_bfloat16*)p_wol,
            b_out, out, CDIM);
    }
}

// round 16
// speedup vs baseline: 1.6827x; 1.0977x over previous
#include <cuda_runtime.h>
#include <cuda_fp16.h>
#include <math.h>
#include <stdint.h>

#define BSZ 2
#define TSEQ 2048
#define CDIM 1024
#define NHEAD 16
#define HDIM 64
#define EPS 1e-6f
#define LN2F 0.69314718056f

#define MTOT (BSZ * TSEQ)          // 4096
#define N1 (3 * CDIM)              // 3072
#define KD CDIM                    // 1024

typedef unsigned long long u64;
typedef unsigned short u16;

// ---------------------------------------------------------------------------
// Scratch (__device__ globals; no allocation allowed). All splits are fp16.
// ---------------------------------------------------------------------------
__device__ u16 g_xhi[(size_t)MTOT * KD];
__device__ u16 g_xlo[(size_t)MTOT * KD];
__device__ u16 g_wqkvT_hi[(size_t)N1 * KD];
__device__ u16 g_wqkvT_lo[(size_t)N1 * KD];
__device__ u16 g_woT_hi[(size_t)CDIM * KD];
__device__ u16 g_woT_lo[(size_t)CDIM * KD];
__device__ u16 g_atthi[(size_t)MTOT * KD];
__device__ u16 g_attlo[(size_t)MTOT * KD];

// attention operands: [b*H+h][t][64] fp16 hi/lo + row sq-norms (PRE-SCALED by ln2)
#define BHT ((size_t)BSZ * NHEAD * TSEQ)
__device__ u16 g_qhi[BHT * HDIM];
__device__ u16 g_qlo[BHT * HDIM];
__device__ u16 g_khi[BHT * HDIM];
__device__ u16 g_klo[BHT * HDIM];
__device__ u16 g_vhi[BHT * HDIM];
__device__ u16 g_vlo[BHT * HDIM];
__device__ float g_qsq[BHT];       // |q|^2 * ln2
__device__ float g_ksq[BHT];       // |k|^2 * ln2

// ---------------------------------------------------------------------------
// PTX helpers (baseline sm_80+ / sm_100-family f32x2 — compute_103-safe)
// ---------------------------------------------------------------------------
__device__ __forceinline__ uint32_t smem_u32(const void* p) {
    uint32_t a;
    asm("{ .reg .u64 t; cvta.to.shared.u64 t, %1; cvt.u32.u64 %0, t; }"
        : "=r"(a) : "l"(p));
    return a;
}

#define CP16(dst, src) \
    asm volatile("cp.async.cg.shared.global [%0], [%1], 16;" \
                 :: "r"(dst), "l"(src))
#define CP_COMMIT() asm volatile("cp.async.commit_group;" ::: "memory")
#define CP_WAIT(n)  asm volatile("cp.async.wait_group %0;" :: "n"(n) : "memory")

__device__ __forceinline__ void ldsm_x4(uint32_t* r, uint32_t addr) {
    asm volatile("ldmatrix.sync.aligned.m8n8.x4.shared.b16 {%0,%1,%2,%3}, [%4];"
                 : "=r"(r[0]), "=r"(r[1]), "=r"(r[2]), "=r"(r[3]) : "r"(addr));
}
__device__ __forceinline__ void ldsm_x4t(uint32_t* r, uint32_t addr) {
    asm volatile("ldmatrix.sync.aligned.m8n8.x4.trans.shared.b16 {%0,%1,%2,%3}, [%4];"
                 : "=r"(r[0]), "=r"(r[1]), "=r"(r[2]), "=r"(r[3]) : "r"(addr));
}

// fp16 HMMA: D += A * B^T (m16n8k16)
__device__ __forceinline__ void mma16816(float* c, const uint32_t* a, const uint32_t* b) {
    asm volatile(
        "mma.sync.aligned.m16n8k16.row.col.f32.f16.f16.f32 "
        "{%0,%1,%2,%3}, {%4,%5,%6,%7}, {%8,%9}, {%0,%1,%2,%3};"
        : "+f"(c[0]), "+f"(c[1]), "+f"(c[2]), "+f"(c[3])
        : "r"(a[0]), "r"(a[1]), "r"(a[2]), "r"(a[3]), "r"(b[0]), "r"(b[1]));
}

__device__ __forceinline__ uint32_t pack_f16x2(float hi, float lo) {
    uint32_t r;
    asm("cvt.rn.f16x2.f32 %0, %1, %2;" : "=r"(r) : "f"(hi), "f"(lo));
    return r;
}
__device__ __forceinline__ void unpack_f16x2(uint32_t v, float& flo, float& fhi) {
    asm("{ .reg .f16 l, h; mov.b32 {l, h}, %2; cvt.f32.f16 %0, l; cvt.f32.f16 %1, h; }"
        : "=f"(flo), "=f"(fhi) : "r"(v));
}
// split pair of fp32 -> fp16 hi pair + fp16 lo (residual) pair
__device__ __forceinline__ uint32_t split_pair_f16(float v0, float v1, uint32_t& lopair) {
    uint32_t hv = pack_f16x2(v1, v0);
    float h0, h1;
    unpack_f16x2(hv, h0, h1);
    lopair = pack_f16x2(v1 - h1, v0 - h0);
    return hv;
}

// ---- packed f32x2 primitives (Blackwell) ----
__device__ __forceinline__ u64 f2pk(float lo, float hi) {
    u64 r; asm("mov.b64 %0, {%1, %2};" : "=l"(r) : "f"(lo), "f"(hi)); return r;
}
__device__ __forceinline__ void f2up(u64 v, float& lo, float& hi) {
    asm("mov.b64 {%0, %1}, %2;" : "=f"(lo), "=f"(hi) : "l"(v));
}
__device__ __forceinline__ u64 f2bcast(float x) { return f2pk(x, x); }
__device__ __forceinline__ u64 f2fma(u64 a, u64 b, u64 c) {
    u64 r; asm("fma.rn.f32x2 %0, %1, %2, %3;" : "=l"(r) : "l"(a), "l"(b), "l"(c)); return r;
}
__device__ __forceinline__ u64 f2mul(u64 a, u64 b) {
    u64 r; asm("mul.rn.f32x2 %0, %1, %2;" : "=l"(r) : "l"(a), "l"(b)); return r;
}
__device__ __forceinline__ u64 f2add(u64 a, u64 b) {
    u64 r; asm("add.rn.f32x2 %0, %1, %2;" : "=l"(r) : "l"(a), "l"(b)); return r;
}

// packed reciprocal: bit trick + 2 Newton (rel err ~1.3e-6, d > 0)
__device__ __forceinline__ u64 f2rcp(u64 d, u64 TWOP, u64 NEG1P) {
    float dl, dh; f2up(d, dl, dh);
    u64 y = f2pk(__uint_as_float(0x7EF311C3u - __float_as_uint(dl)),
                 __uint_as_float(0x7EF311C3u - __float_as_uint(dh)));
    u64 nd = f2mul(d, NEG1P);
    y = f2mul(y, f2fma(nd, y, TWOP));
    y = f2mul(y, f2fma(nd, y, TWOP));
    return y;
}

// packed exp2 (x <= 0): magic round + deg-5 poly; exponent clamp in int domain
__device__ __forceinline__ void f2exp2(u64 x, u64 MAGICP, u64 NEG1P,
                                       u64 PC5, u64 PC4, u64 PC3, u64 PC2, u64 PC1, u64 PC0,
                                       float& r0, float& r1) {
    u64 tt = f2add(x, MAGICP);
    u64 nn = f2fma(MAGICP, NEG1P, tt);
    u64 ff = f2fma(nn, NEG1P, x);
    u64 p = f2fma(PC5, ff, PC4);
    p = f2fma(p, ff, PC3);
    p = f2fma(p, ff, PC2);
    p = f2fma(p, ff, PC1);
    p = f2fma(p, ff, PC0);
    float tl, th, pl_, ph_;
    f2up(tt, tl, th);
    f2up(p, pl_, ph_);
    int il = max(__float_as_int(tl) - 0x4B400000, -127);
    int ih = max(__float_as_int(th) - 0x4B400000, -127);
    r0 = __int_as_float(__float_as_int(pl_) + (il << 23));
    r1 = __int_as_float(__float_as_int(ph_) + (ih << 23));
}

// scalar exp2 (rescale path only)
__device__ __forceinline__ float exp2_fast(float x) {
    x = fmaxf(x, -126.f);
    float t = x + 12582912.f;
    int   i = __float_as_int(t) - 0x4B400000;
    float f = x - (t - 12582912.f);
    float p =            1.33336498e-3f;
    p = fmaf(p, f, 9.61793571e-3f);
    p = fmaf(p, f, 5.55041087e-2f);
    p = fmaf(p, f, 2.40226507e-1f);
    p = fmaf(p, f, 6.93147182e-1f);
    p = fmaf(p, f, 1.0f);
    return __int_as_float(__float_as_int(p) + (i << 23));
}

// ---------------------------------------------------------------------------
// Pre-pass: split fp32 -> fp16 hi/lo (elementwise)
// ---------------------------------------------------------------------------
__global__ void split_kernel(const float* __restrict__ src,
                             u16* __restrict__ hi, u16* __restrict__ lo, int n4) {
    int i = blockIdx.x * blockDim.x + threadIdx.x;
    if (i >= n4) return;
    float4 v = ((const float4*)src)[i];
    float a[4] = {v.x, v.y, v.z, v.w};
    ushort4 hv, lv;
    u16* hp = &hv.x;
    u16* lp = &lv.x;
#pragma unroll
    for (int j = 0; j < 4; j++) {
        __half h = __float2half(a[j]);
        float r = a[j] - __half2float(h);
        __half l = __float2half(r);
        hp[j] = __half_as_ushort(h);
        lp[j] = __half_as_ushort(l);
    }
    ((ushort4*)hi)[i] = hv;
    ((ushort4*)lo)[i] = lv;
}

// ---------------------------------------------------------------------------
// Pre-pass: transpose + split  W[K,N] fp32 -> Wt_hi/lo[N,K] fp16 (vectorized)
// ---------------------------------------------------------------------------
__global__ __launch_bounds__(256)
void transpose_split_kernel(const float* __restrict__ W,
                            u16* __restrict__ hi, u16* __restrict__ lo, int K, int N) {
    __shared__ float tile[32][33];
    int n0 = blockIdx.x * 32, k0 = blockIdx.y * 32;
    int t = threadIdx.x;
#pragma unroll
    for (int i = 0; i < 4; i++) {
        int idx = t + i * 256;
        int kk = idx >> 5, nn = idx & 31;
        tile[kk][nn] = W[(size_t)(k0 + kk) * N + n0 + nn];
    }
    __syncthreads();
    int n = t >> 3, kg = t & 7;
    ushort4 hv, lv;
    u16* hp = &hv.x;
    u16* lp = &lv.x;
#pragma unroll
    for (int j = 0; j < 4; j++) {
        float v = tile[kg * 4 + j][n];
        __half h = __float2half(v);
        float r = v - __half2float(h);
        __half l = __float2half(r);
        hp[j] = __half_as_ushort(h);
        lp[j] = __half_as_ushort(l);
    }
    size_t o = ((size_t)(n0 + n) * K + k0 + kg * 4) >> 2;
    ((ushort4*)hi)[o] = hv;
    ((ushort4*)lo)[o] = lv;
}

// ---------------------------------------------------------------------------
// sq-norm kernel: |row|^2 * ln2 (q and k), fp16 hi+lo reconstruction
// ---------------------------------------------------------------------------
__global__ __launch_bounds__(256)
void sqnorm_kernel() {
    const uint32_t* hi = blockIdx.y ? (const uint32_t*)g_khi : (const uint32_t*)g_qhi;
    const uint32_t* lo = blockIdx.y ? (const uint32_t*)g_klo : (const uint32_t*)g_qlo;
    float* out = blockIdx.y ? g_ksq : g_qsq;
    size_t gw = (size_t)blockIdx.x * 8 + (threadIdx.x >> 5);
    int lane = threadIdx.x & 31;
    uint32_t h = hi[gw * 32 + lane], l = lo[gw * 32 + lane];
    float h0, h1, l0v, l1v;
    unpack_f16x2(h, h0, h1);
    unpack_f16x2(l, l0v, l1v);
    float f0 = h0 + l0v, f1 = h1 + l1v;
    float s = fmaf(f0, f0, f1 * f1);
#pragma unroll
    for (int o = 16; o; o >>= 1) s += __shfl_xor_sync(0xffffffffu, s, o);
    if (lane == 0) out[gw] = s * LN2F;
}

// ---------------------------------------------------------------------------
// HMMA GEMM mainloop: 3-stage cp.async, 1 barrier/k-tile. NT = split terms.
// NT=3: AhBh+AhBl+AlBh.  NT=2: AhBh+AhBl (Al never loaded).
// ---------------------------------------------------------------------------
#define TILE64 (128 * 64)
#define STG64  (4 * TILE64)
#define GEMM_SMEM (3 * STG64)
#define NKT (KD / 32)

#define SWZ(r, c) ((uint32_t)((r) * 64 + ((((c) + ((r) >> 1)) & 3) << 4)))

template <int NT>
__device__ __forceinline__ void g2s_stage(uint32_t sdst,
                                          const u16* Ah, const u16* Al,
                                          const u16* Bh, const u16* Bl,
                                          int m0, int n0, int k0, int t) {
#pragma unroll
    for (int i = 0; i < 2; i++) {
        int idx = t + i * 256;
        int r = idx >> 2;
        int c = idx & 3;
        uint32_t soff = SWZ(r, c);
        size_t ga = (size_t)(m0 + r) * KD + k0 + c * 8;
        size_t gb = (size_t)(n0 + r) * KD + k0 + c * 8;
        CP16(sdst + soff,              (const char*)(Ah + ga));
        if (NT == 3)
            CP16(sdst + TILE64 + soff, (const char*)(Al + ga));
        CP16(sdst + 2 * TILE64 + soff, (const char*)(Bh + gb));
        CP16(sdst + 3 * TILE64 + soff, (const char*)(Bl + gb));
    }
}

template <int NT>
__device__ __forceinline__ void gemm_mainloop(
        uint32_t sb, const u16* Ah, const u16* Al,
        const u16* Bh, const u16* Bl,
        int m0, int n0, int t, float acc[4][4][4]) {
    const int lane = t & 31;
    const int w    = t >> 5;
    const int wm   = w & 1;
    const int wn   = w >> 1;
    const int g    = lane >> 3;

    uint32_t st0 = sb, st1 = sb + STG64, st2 = sb + 2 * STG64;

    g2s_stage<NT>(st0, Ah, Al, Bh, Bl, m0, n0, 0,  t); CP_COMMIT();
    g2s_stage<NT>(st1, Ah, Al, Bh, Bl, m0, n0, 32, t); CP_COMMIT();

    for (int kt = 0; kt < NKT; kt++) {
        if (kt == NKT - 1) { CP_WAIT(0); } else { CP_WAIT(1); }
        __syncthreads();
        if (kt + 2 < NKT) {
            g2s_stage<NT>(st2, Ah, Al, Bh, Bl, m0, n0, (kt + 2) * 32, t);
            CP_COMMIT();
        }

#pragma unroll
        for (int ks = 0; ks < 2; ks++) {
            uint32_t ah[4][4], al[4][4];
#pragma unroll
            for (int mi = 0; mi < 4; mi++) {
                int row = wm * 64 + mi * 16 + (lane & 15);
                int c   = ks * 2 + (lane >> 4);
                uint32_t ra = st0 + SWZ(row, c);
                ldsm_x4(ah[mi], ra);
                if (NT == 3) ldsm_x4(al[mi], ra + TILE64);
            }
            uint32_t bh[4][2], bl[4][2];
#pragma unroll
            for (int nb = 0; nb < 2; nb++) {
                int row = wn * 32 + nb * 16 + (g >> 1) * 8 + (lane & 7);
                int c   = ks * 2 + (g & 1);
                uint32_t rb = st0 + 2 * TILE64 + SWZ(row, c);
                ldsm_x4(&bh[2 * nb][0], rb);
                ldsm_x4(&bl[2 * nb][0], rb + TILE64);
            }
#pragma unroll
            for (int mi = 0; mi < 4; mi++)
#pragma unroll
                for (int ni = 0; ni < 4; ni++) mma16816(acc[mi][ni], ah[mi], bh[ni]);
#pragma unroll
            for (int mi = 0; mi < 4; mi++)
#pragma unroll
                for (int ni = 0; ni < 4; ni++) mma16816(acc[mi][ni], ah[mi], bl[ni]);
            if (NT == 3) {
#pragma unroll
                for (int mi = 0; mi < 4; mi++)
#pragma unroll
                    for (int ni = 0; ni < 4; ni++) mma16816(acc[mi][ni], al[mi], bh[ni]);
            }
        }
        uint32_t tmp = st0; st0 = st1; st1 = st2; st2 = tmp;
    }
}

// GEMM2: 2-term split, plain fp32 + bias epilogue (writes final output)
__global__ __launch_bounds__(256, 2)
void mma_gemm_kernel(const u16* __restrict__ Ah, const u16* __restrict__ Al,
                     const u16* __restrict__ Bh, const u16* __restrict__ Bl,
                     const float* __restrict__ bias,
                     float* __restrict__ C, int N) {
    extern __shared__ char smem[];
    const uint32_t sb = smem_u32(smem);
    const int t = threadIdx.x, lane = t & 31, w = t >> 5;
    const int wm = w & 1, wn = w >> 1;
    const int m0 = blockIdx.y * 128, n0 = blockIdx.x * 128;

    float acc[4][4][4];
#pragma unroll
    for (int mi = 0; mi < 4; mi++)
#pragma unroll
        for (int ni = 0; ni < 4; ni++)
#pragma unroll
            for (int r = 0; r < 4; r++) acc[mi][ni][r] = 0.f;

    gemm_mainloop<2>(sb, Ah, Al, Bh, Bl, m0, n0, t, acc);

#pragma unroll
    for (int mi = 0; mi < 4; mi++) {
        int row = m0 + wm * 64 + mi * 16 + (lane >> 2);
#pragma unroll
        for (int ni = 0; ni < 4; ni++) {
            int col = n0 + wn * 32 + ni * 8 + (lane & 3) * 2;
            float b0 = bias[col], b1 = bias[col + 1];
            float2 v0 = {acc[mi][ni][0] + b0, acc[mi][ni][1] + b1};
            float2 v1 = {acc[mi][ni][2] + b0, acc[mi][ni][3] + b1};
            *(float2*)&C[(size_t)row * N + col]       = v0;
            *(float2*)&C[(size_t)(row + 8) * N + col] = v1;
        }
    }
}

// GEMM1: 3-term split, fused epilogue -> per-head fp16 hi/lo q/k/v
__global__ __launch_bounds__(256, 2)
void mma_gemm_qkv_kernel(const u16* __restrict__ Ah, const u16* __restrict__ Al,
                         const u16* __restrict__ Bh, const u16* __restrict__ Bl,
                         const float* __restrict__ bias) {
    extern __shared__ char smem[];
    const uint32_t sb = smem_u32(smem);
    const int t = threadIdx.x, lane = t & 31, w = t >> 5;
    const int wm = w & 1, wn = w >> 1;
    const int m0 = blockIdx.y * 128, n0 = blockIdx.x * 128;

    float acc[4][4][4];
#pragma unroll
    for (int mi = 0; mi < 4; mi++)
#pragma unroll
        for (int ni = 0; ni < 4; ni++)
#pragma unroll
            for (int r = 0; r < 4; r++) acc[mi][ni][r] = 0.f;

    gemm_mainloop<3>(sb, Ah, Al, Bh, Bl, m0, n0, t, acc);

    const int sec = n0 >> 10;     // 0=q, 1=k, 2=v
    uint32_t* ph = sec == 0 ? (uint32_t*)g_qhi : sec == 1 ? (uint32_t*)g_khi : (uint32_t*)g_vhi;
    uint32_t* pl = sec == 0 ? (uint32_t*)g_qlo : sec == 1 ? (uint32_t*)g_klo : (uint32_t*)g_vlo;

#pragma unroll
    for (int mi = 0; mi < 4; mi++) {
        int row = m0 + wm * 64 + mi * 16 + (lane >> 2);
        int b   = row >> 11, tok = row & (TSEQ - 1);
#pragma unroll
        for (int ni = 0; ni < 4; ni++) {
            int col  = n0 + wn * 32 + ni * 8 + (lane & 3) * 2;
            int head = (col >> 6) & (NHEAD - 1);
            int d    = col & 63;
            size_t base = ((size_t)(b * NHEAD + head) * TSEQ) * 32 + (d >> 1);
            float b0 = bias[col], b1 = bias[col + 1];
#pragma unroll
            for (int r2 = 0; r2 < 2; r2++) {
                float v0 = acc[mi][ni][2 * r2]     + b0;
                float v1 = acc[mi][ni][2 * r2 + 1] + b1;
                uint32_t lv;
                uint32_t hv = split_pair_f16(v0, v1, lv);
                size_t idx = base + (size_t)(tok + r2 * 8) * 32;
                ph[idx] = hv;
                pl[idx] = lv;
            }
        }
    }
}

// ---------------------------------------------------------------------------
// FlashAttention-style Yat attention (round-15 winner structure) with fp16:
// QK 3-term, PV 2-term (P-hi only), fp16-split epilogue.
// ---------------------------------------------------------------------------
#define AROWB 144
#define QLOFF  18432
#define SBASE  36864
#define KLOFF  9216
#define VHOFF  18432
#define VLOFF  27648
#define KSQOFF 36864
#define ASTG   37120
#define ATT_SMEM (SBASE + 2 * ASTG)

__device__ __forceinline__ void load_kv(uint32_t dst,
                                        const char* kh, const char* kl,
                                        const char* vh, const char* vl,
                                        const char* ksq, int kt, int t) {
#pragma unroll
    for (int i = 0; i < 2; i++) {
        int idx = t + i * 256;
        int rr = idx >> 3, cc = idx & 7;
        uint32_t off = (uint32_t)(rr * AROWB + cc * 16);
        size_t gbyte = ((size_t)(kt * 64 + rr) * HDIM + cc * 8) * 2;
        CP16(dst + off,         kh + gbyte);
        CP16(dst + KLOFF + off, kl + gbyte);
        CP16(dst + VHOFF + off, vh + gbyte);
        CP16(dst + VLOFF + off, vl + gbyte);
    }
    if (t < 16) CP16(dst + KSQOFF + t * 16, ksq + (size_t)kt * 64 * 4 + t * 16);
}

__global__ __launch_bounds__(256, 2)
void yat_attn_mma() {
    extern __shared__ char smem[];
    const uint32_t sb = smem_u32(smem);

    const int t = threadIdx.x, lane = t & 31, w = t >> 5;
    const int h = blockIdx.y, b = blockIdx.z;
    const int qt = gridDim.x - 1 - blockIdx.x;
    const int q0 = qt * 128;
    const int bh = b * NHEAD + h;
    const size_t hb = (size_t)bh * TSEQ * HDIM;

    const char* pQh = (const char*)(g_qhi + hb);
    const char* pQl = (const char*)(g_qlo + hb);
    const char* pKh = (const char*)(g_khi + hb);
    const char* pKl = (const char*)(g_klo + hb);
    const char* pVh = (const char*)(g_vhi + hb);
    const char* pVl = (const char*)(g_vlo + hb);
    const char* pKs = (const char*)(g_ksq + (size_t)bh * TSEQ);

    const int nkt = 2 * qt + 2;

#pragma unroll
    for (int i = 0; i < 4; i++) {
        int idx = t + i * 256;
        int r = idx >> 3, c = idx & 7;
        uint32_t d = sb + (uint32_t)(r * AROWB + c * 16);
        size_t gbyte = ((size_t)(q0 + r) * HDIM + c * 8) * 2;
        CP16(d,          pQh + gbyte);
        CP16(d + QLOFF,  pQl + gbyte);
    }
    CP_COMMIT();
    load_kv(sb + SBASE,        pKh, pKl, pVh, pVl, pKs, 0, t); CP_COMMIT();
    load_kv(sb + SBASE + ASTG, pKh, pKl, pVh, pVl, pKs, 1, t); CP_COMMIT();

    const int rl  = lane >> 2;
    const int rg0 = q0 + w * 16 + rl;
    const int rg1 = rg0 + 8;
    const float qa0 = g_qsq[(size_t)bh * TSEQ + rg0] + EPS * LN2F;
    const float qa1 = g_qsq[(size_t)bh * TSEQ + rg1] + EPS * LN2F;

    const u64 MAGICP = f2bcast(12582912.f);
    const u64 NEG1P  = f2bcast(-1.f);
    const u64 TWOP   = f2bcast(2.f);
    const u64 C2P    = f2bcast(-2.f * LN2F);
    const u64 PC5 = f2bcast(1.33336498e-3f);
    const u64 PC4 = f2bcast(9.61793571e-3f);
    const u64 PC3 = f2bcast(5.55041087e-2f);
    const u64 PC2 = f2bcast(2.40226507e-1f);
    const u64 PC1 = f2bcast(6.93147182e-1f);
    const u64 PC0 = f2bcast(1.0f);
    const u64 QA0P = f2bcast(qa0);
    const u64 QA1P = f2bcast(qa1);

    float O[8][4];
#pragma unroll
    for (int dt = 0; dt < 8; dt++)
#pragma unroll
        for (int r = 0; r < 4; r++) O[dt][r] = 0.f;
    float m0 = -1e30f, m1 = -1e30f, l0 = 0.f, l1 = 0.f;

    for (int i = 0; i < nkt; i++) {
        if (i == nkt - 1) { CP_WAIT(0); } else { CP_WAIT(1); }
        __syncthreads();

        const uint32_t kb = sb + SBASE + (uint32_t)(i & 1) * ASTG;
        const char* kbp = smem + SBASE + (size_t)(i & 1) * ASTG;
        const float* ksqp = (const float*)(kbp + KSQOFF);
        const int k0 = i * 64;
        const bool need_mask = (k0 + 63 > q0 + w * 16);

        // ---- S = Q K^T (3-term fp16 split) ----
        float S[8][4];
#pragma unroll
        for (int nt = 0; nt < 8; nt++)
#pragma unroll
            for (int r = 0; r < 4; r++) S[nt][r] = 0.f;

        const int g = lane >> 3;
#pragma unroll
        for (int ks = 0; ks < 4; ks++) {
            uint32_t ah[4], al[4];
            uint32_t qaddr = sb + (uint32_t)((w * 16 + (lane & 15)) * AROWB
                                             + ks * 32 + (lane >> 4) * 16);
            ldsm_x4(ah, qaddr);
            ldsm_x4(al, qaddr + QLOFF);
#pragma unroll
            for (int nbp = 0; nbp < 4; nbp += 2) {
                uint32_t bhA[4], blA[4], bhB[4], blB[4];
                uint32_t kaddrA = kb + (uint32_t)((nbp * 16 + (g >> 1) * 8 + (lane & 7)) * AROWB
                                                  + ks * 32 + (g & 1) * 16);
                uint32_t kaddrB = kaddrA + 16 * AROWB;
                ldsm_x4(bhA, kaddrA);
                ldsm_x4(blA, kaddrA + KLOFF);
                ldsm_x4(bhB, kaddrB);
                ldsm_x4(blB, kaddrB + KLOFF);
                mma16816(S[2 * nbp],     ah, bhA);
                mma16816(S[2 * nbp + 1], ah, bhA + 2);
                mma16816(S[2 * nbp + 2], ah, bhB);
                mma16816(S[2 * nbp + 3], ah, bhB + 2);
                mma16816(S[2 * nbp],     al, bhA);
                mma16816(S[2 * nbp + 1], al, bhA + 2);
                mma16816(S[2 * nbp + 2], al, bhB);
                mma16816(S[2 * nbp + 3], al, bhB + 2);
                mma16816(S[2 * nbp],     ah, blA);
                mma16816(S[2 * nbp + 1], ah, blA + 2);
                mma16816(S[2 * nbp + 2], ah, blB);
                mma16816(S[2 * nbp + 3], ah, blB + 2);
            }
        }

        // ---- scores + mask + max (packed f32x2) ----
        u64 SP[8][2];
        float mx0 = -1e30f, mx1 = -1e30f;
#pragma unroll
        for (int nt = 0; nt < 8; nt++) {
            int cb = nt * 8 + 2 * (lane & 3);
            float2 ksv = *(const float2*)&ksqp[cb];
            u64 kpp = f2pk(ksv.x, ksv.y);
            u64 d0 = f2pk(S[nt][0], S[nt][1]);
            u64 d1 = f2pk(S[nt][2], S[nt][3]);
            u64 den0 = f2fma(C2P, d0, f2add(QA0P, kpp));
            u64 den1 = f2fma(C2P, d1, f2add(QA1P, kpp));
            u64 sl0 = f2mul(f2mul(d0, d0), f2rcp(den0, TWOP, NEG1P));
            u64 sl1 = f2mul(f2mul(d1, d1), f2rcp(den1, TWOP, NEG1P));
            float a0, a1, b0, b1;
            f2up(sl0, a0, a1);
            f2up(sl1, b0, b1);
            if (need_mask) {
                int cg = k0 + cb;
                if (cg > rg0)     a0 = -1e30f;
                if (cg + 1 > rg0) a1 = -1e30f;
                if (cg > rg1)     b0 = -1e30f;
                if (cg + 1 > rg1) b1 = -1e30f;
            }
            mx0 = fmaxf(mx0, fmaxf(a0, a1));
            mx1 = fmaxf(mx1, fmaxf(b0, b1));
            SP[nt][0] = f2pk(a0, a1);
            SP[nt][1] = f2pk(b0, b1);
        }
        mx0 = fmaxf(mx0, __shfl_xor_sync(0xffffffffu, mx0, 1));
        mx0 = fmaxf(mx0, __shfl_xor_sync(0xffffffffu, mx0, 2));
        mx1 = fmaxf(mx1, __shfl_xor_sync(0xffffffffu, mx1, 1));
        mx1 = fmaxf(mx1, __shfl_xor_sync(0xffffffffu, mx1, 2));
        float mn0 = fmaxf(m0, mx0), mn1 = fmaxf(m1, mx1);
        float sc0 = exp2_fast(m0 - mn0), sc1 = exp2_fast(m1 - mn1);
        m0 = mn0; m1 = mn1;
        if (__any_sync(0xffffffffu, (sc0 != 1.f) || (sc1 != 1.f))) {
            l0 *= sc0; l1 *= sc1;
#pragma unroll
            for (int dt = 0; dt < 8; dt++) {
                O[dt][0] *= sc0; O[dt][1] *= sc0;
                O[dt][2] *= sc1; O[dt][3] *= sc1;
            }
        }

        // ---- p = exp2(sl - m) (packed), fp16 hi only ----
        const u64 NM0 = f2bcast(-mn0);
        const u64 NM1 = f2bcast(-mn1);
        uint32_t pH[8][2];
#pragma unroll
        for (int nt = 0; nt < 8; nt++) {
            float p0, p1, p2, p3;
            f2exp2(f2add(SP[nt][0], NM0), MAGICP, NEG1P, PC5, PC4, PC3, PC2, PC1, PC0, p0, p1);
            f2exp2(f2add(SP[nt][1], NM1), MAGICP, NEG1P, PC5, PC4, PC3, PC2, PC1, PC0, p2, p3);
            l0 += p0 + p1;
            l1 += p2 + p3;
            pH[nt][0] = pack_f16x2(p1, p0);
            pH[nt][1] = pack_f16x2(p3, p2);
        }

        // ---- O += P (Vh + Vl), 2-term ----
        const int vrow = (lane & 7) + ((lane >> 3) & 1) * 8;
        const int vcol = ((lane >> 4) & 1) * 16;
#pragma unroll
        for (int kc = 0; kc < 4; kc++) {
            uint32_t aH[4] = {pH[2 * kc][0], pH[2 * kc][1], pH[2 * kc + 1][0], pH[2 * kc + 1][1]};
#pragma unroll
            for (int dpp = 0; dpp < 4; dpp += 2) {
                uint32_t vaddrA = kb + VHOFF
                                + (uint32_t)((kc * 16 + vrow) * AROWB + dpp * 32 + vcol);
                uint32_t vaddrB = vaddrA + 32;
                uint32_t vhA[4], vlA[4], vhB[4], vlB[4];
                ldsm_x4t(vhA, vaddrA);
                ldsm_x4t(vlA, vaddrA + KLOFF);
                ldsm_x4t(vhB, vaddrB);
                ldsm_x4t(vlB, vaddrB + KLOFF);
                mma16816(O[2 * dpp],     aH, vhA);
                mma16816(O[2 * dpp + 1], aH, vhA + 2);
                mma16816(O[2 * dpp + 2], aH, vhB);
                mma16816(O[2 * dpp + 3], aH, vhB + 2);
                mma16816(O[2 * dpp],     aH, vlA);
                mma16816(O[2 * dpp + 1], aH, vlA + 2);
                mma16816(O[2 * dpp + 2], aH, vlB);
                mma16816(O[2 * dpp + 3], aH, vlB + 2);
            }
        }

        __syncthreads();
        if (i + 2 < nkt) {
            load_kv(kb, pKh, pKl, pVh, pVl, pKs, i + 2, t);
            CP_COMMIT();
        }
    }

    // ---- finalize: normalize, fp16 hi/lo split, store ----
    l0 += __shfl_xor_sync(0xffffffffu, l0, 1);
    l0 += __shfl_xor_sync(0xffffffffu, l0, 2);
    l1 += __shfl_xor_sync(0xffffffffu, l1, 1);
    l1 += __shfl_xor_sync(0xffffffffu, l1, 2);
    float i0 = __fdividef(1.f, l0);
    float i1 = __fdividef(1.f, l1);

    uint32_t* oh = (uint32_t*)g_atthi;
    uint32_t* ol = (uint32_t*)g_attlo;
    size_t base0 = (((size_t)(b * TSEQ + rg0)) * CDIM + h * HDIM + 2 * (lane & 3)) >> 1;
    size_t base1 = (((size_t)(b * TSEQ + rg1)) * CDIM + h * HDIM + 2 * (lane & 3)) >> 1;
#pragma unroll
    for (int dt = 0; dt < 8; dt++) {
        float v0 = O[dt][0] * i0, v1 = O[dt][1] * i0;
        float v2 = O[dt][2] * i1, v3 = O[dt][3] * i1;
        uint32_t lv0, lv1;
        uint32_t hv0 = split_pair_f16(v0, v1, lv0);
        uint32_t hv1 = split_pair_f16(v2, v3, lv1);
        oh[base0 + dt * 4] = hv0;
        ol[base0 + dt * 4] = lv0;
        oh[base1 + dt * 4] = hv1;
        ol[base1 + dt * 4] = lv1;
    }
}

// ---------------------------------------------------------------------------
// Launch
// ---------------------------------------------------------------------------
extern "C" void kernel_launch(void* const* d_in, const int* in_sizes, int n_in,
                              void* d_out, int out_size) {
    const float* x     = (const float*)d_in[0];
    const float* w_qkv = (const float*)d_in[1];
    const float* b_qkv = (const float*)d_in[2];
    const float* w_out = (const float*)d_in[3];
    const float* b_out = (const float*)d_in[4];
    float* out = (float*)d_out;

    void *p_xhi, *p_xlo, *p_wqh, *p_wql, *p_woh, *p_wol, *p_ahi, *p_alo;
    cudaGetSymbolAddress(&p_xhi, g_xhi);
    cudaGetSymbolAddress(&p_xlo, g_xlo);
    cudaGetSymbolAddress(&p_wqh, g_wqkvT_hi);
    cudaGetSymbolAddress(&p_wql, g_wqkvT_lo);
    cudaGetSymbolAddress(&p_woh, g_woT_hi);
    cudaGetSymbolAddress(&p_wol, g_woT_lo);
    cudaGetSymbolAddress(&p_ahi, g_atthi);
    cudaGetSymbolAddress(&p_alo, g_attlo);

    static bool attr_done = false;
    if (!attr_done) {
        cudaFuncSetAttribute(mma_gemm_kernel,
                             cudaFuncAttributeMaxDynamicSharedMemorySize, GEMM_SMEM);
        cudaFuncSetAttribute(mma_gemm_qkv_kernel,
                             cudaFuncAttributeMaxDynamicSharedMemorySize, GEMM_SMEM);
        cudaFuncSetAttribute(yat_attn_mma,
                             cudaFuncAttributeMaxDynamicSharedMemorySize, ATT_SMEM);
        attr_done = true;
    }

    // 0) split x, transpose+split weights (fp16)
    {
        int n4 = MTOT * KD / 4;
        split_kernel<<<(n4 + 255) / 256, 256>>>(x, (u16*)p_xhi, (u16*)p_xlo, n4);
        dim3 g1(N1 / 32, KD / 32);
        transpose_split_kernel<<<g1, 256>>>(w_qkv, (u16*)p_wqh, (u16*)p_wql, KD, N1);
        dim3 g2(CDIM / 32, KD / 32);
        transpose_split_kernel<<<g2, 256>>>(w_out, (u16*)p_woh, (u16*)p_wol, KD, CDIM);
    }

    // 1) QKV projection (3-term), fused epilogue -> per-head fp16 splits
    {
        dim3 grid(N1 / 128, MTOT / 128);
        mma_gemm_qkv_kernel<<<grid, 256, GEMM_SMEM>>>(
            (const u16*)p_xhi, (const u16*)p_xlo,
            (const u16*)p_wqh, (const u16*)p_wql, b_qkv);
    }

    // 2) sq-norms (ln2-scaled) + HMMA flash attention
    {
        dim3 gs((unsigned)(BHT / 8), 2);
        sqnorm_kernel<<<gs, 256>>>();
        dim3 grid(TSEQ / 128, NHEAD, BSZ);
        yat_attn_mma<<<grid, 256, ATT_SMEM>>>();
    }

    // 3) output projection (2-term)
    {
        dim3 grid(CDIM / 128, MTOT / 128);
        mma_gemm_kernel<<<grid, 256, GEMM_SMEM>>>(
            (const u16*)p_ahi, (const u16*)p_alo,
            (const u16*)p_woh, (const u16*)p_wol,
            b_out, out, CDIM);
    }
}

// round 17
// speedup vs baseline: 1.9452x; 1.1560x over previous
#include <cuda_runtime.h>
#include <cuda_fp16.h>
#include <math.h>
#include <stdint.h>

#define BSZ 2
#define TSEQ 2048
#define CDIM 1024
#define NHEAD 16
#define HDIM 64
#define EPS 1e-6f
#define LN2F 0.69314718056f

#define MTOT (BSZ * TSEQ)          // 4096
#define N1 (3 * CDIM)              // 3072
#define KD CDIM                    // 1024

typedef unsigned long long u64;
typedef unsigned short u16;

// ---------------------------------------------------------------------------
// Scratch (__device__ globals; no allocation allowed). All splits are fp16.
// ---------------------------------------------------------------------------
__device__ u16 g_xhi[(size_t)MTOT * KD];
__device__ u16 g_xlo[(size_t)MTOT * KD];
__device__ u16 g_wqkvT_hi[(size_t)N1 * KD];
__device__ u16 g_wqkvT_lo[(size_t)N1 * KD];
__device__ u16 g_woT_hi[(size_t)CDIM * KD];
__device__ u16 g_woT_lo[(size_t)CDIM * KD];
__device__ u16 g_atthi[(size_t)MTOT * KD];
__device__ u16 g_attlo[(size_t)MTOT * KD];

// attention operands: [b*H+h][t][64] fp16 hi/lo + row sq-norms (PRE-SCALED by ln2)
#define BHT ((size_t)BSZ * NHEAD * TSEQ)
__device__ u16 g_qhi[BHT * HDIM];
__device__ u16 g_qlo[BHT * HDIM];
__device__ u16 g_khi[BHT * HDIM];
__device__ u16 g_klo[BHT * HDIM];
__device__ u16 g_vhi[BHT * HDIM];
__device__ u16 g_vlo[BHT * HDIM];
__device__ float g_qsq[BHT];       // |q|^2 * ln2
__device__ float g_ksq[BHT];       // |k|^2 * ln2

// ---------------------------------------------------------------------------
// PTX helpers (baseline sm_80+ / sm_100-family f32x2 — compute_103-safe)
// ---------------------------------------------------------------------------
__device__ __forceinline__ uint32_t smem_u32(const void* p) {
    uint32_t a;
    asm("{ .reg .u64 t; cvta.to.shared.u64 t, %1; cvt.u32.u64 %0, t; }"
        : "=r"(a) : "l"(p));
    return a;
}

#define CP16(dst, src) \
    asm volatile("cp.async.cg.shared.global [%0], [%1], 16;" \
                 :: "r"(dst), "l"(src))
#define CP_COMMIT() asm volatile("cp.async.commit_group;" ::: "memory")
#define CP_WAIT(n)  asm volatile("cp.async.wait_group %0;" :: "n"(n) : "memory")

__device__ __forceinline__ void ldsm_x4(uint32_t* r, uint32_t addr) {
    asm volatile("ldmatrix.sync.aligned.m8n8.x4.shared.b16 {%0,%1,%2,%3}, [%4];"
                 : "=r"(r[0]), "=r"(r[1]), "=r"(r[2]), "=r"(r[3]) : "r"(addr));
}
__device__ __forceinline__ void ldsm_x4t(uint32_t* r, uint32_t addr) {
    asm volatile("ldmatrix.sync.aligned.m8n8.x4.trans.shared.b16 {%0,%1,%2,%3}, [%4];"
                 : "=r"(r[0]), "=r"(r[1]), "=r"(r[2]), "=r"(r[3]) : "r"(addr));
}

// fp16 HMMA: D += A * B^T (m16n8k16)
__device__ __forceinline__ void mma16816(float* c, const uint32_t* a, const uint32_t* b) {
    asm volatile(
        "mma.sync.aligned.m16n8k16.row.col.f32.f16.f16.f32 "
        "{%0,%1,%2,%3}, {%4,%5,%6,%7}, {%8,%9}, {%0,%1,%2,%3};"
        : "+f"(c[0]), "+f"(c[1]), "+f"(c[2]), "+f"(c[3])
        : "r"(a[0]), "r"(a[1]), "r"(a[2]), "r"(a[3]), "r"(b[0]), "r"(b[1]));
}

__device__ __forceinline__ uint32_t pack_f16x2(float hi, float lo) {
    uint32_t r;
    asm("cvt.rn.f16x2.f32 %0, %1, %2;" : "=r"(r) : "f"(hi), "f"(lo));
    return r;
}
__device__ __forceinline__ void unpack_f16x2(uint32_t v, float& flo, float& fhi) {
    asm("{ .reg .f16 l, h; mov.b32 {l, h}, %2; cvt.f32.f16 %0, l; cvt.f32.f16 %1, h; }"
        : "=f"(flo), "=f"(fhi) : "r"(v));
}
// split pair of fp32 -> fp16 hi pair + fp16 lo (residual) pair
__device__ __forceinline__ uint32_t split_pair_f16(float v0, float v1, uint32_t& lopair) {
    uint32_t hv = pack_f16x2(v1, v0);
    float h0, h1;
    unpack_f16x2(hv, h0, h1);
    lopair = pack_f16x2(v1 - h1, v0 - h0);
    return hv;
}

// ---- packed f32x2 primitives (Blackwell) ----
__device__ __forceinline__ u64 f2pk(float lo, float hi) {
    u64 r; asm("mov.b64 %0, {%1, %2};" : "=l"(r) : "f"(lo), "f"(hi)); return r;
}
__device__ __forceinline__ void f2up(u64 v, float& lo, float& hi) {
    asm("mov.b64 {%0, %1}, %2;" : "=f"(lo), "=f"(hi) : "l"(v));
}
__device__ __forceinline__ u64 f2bcast(float x) { return f2pk(x, x); }
__device__ __forceinline__ u64 f2fma(u64 a, u64 b, u64 c) {
    u64 r; asm("fma.rn.f32x2 %0, %1, %2, %3;" : "=l"(r) : "l"(a), "l"(b), "l"(c)); return r;
}
__device__ __forceinline__ u64 f2mul(u64 a, u64 b) {
    u64 r; asm("mul.rn.f32x2 %0, %1, %2;" : "=l"(r) : "l"(a), "l"(b)); return r;
}
__device__ __forceinline__ u64 f2add(u64 a, u64 b) {
    u64 r; asm("add.rn.f32x2 %0, %1, %2;" : "=l"(r) : "l"(a), "l"(b)); return r;
}

// packed reciprocal: bit trick + 2 Newton (rel err ~1.3e-6, d > 0)
__device__ __forceinline__ u64 f2rcp(u64 d, u64 TWOP, u64 NEG1P) {
    float dl, dh; f2up(d, dl, dh);
    u64 y = f2pk(__uint_as_float(0x7EF311C3u - __float_as_uint(dl)),
                 __uint_as_float(0x7EF311C3u - __float_as_uint(dh)));
    u64 nd = f2mul(d, NEG1P);
    y = f2mul(y, f2fma(nd, y, TWOP));
    y = f2mul(y, f2fma(nd, y, TWOP));
    return y;
}

// packed exp2 (x <= 0): magic round + deg-5 poly; exponent clamp in int domain
__device__ __forceinline__ void f2exp2(u64 x, u64 MAGICP, u64 NEG1P,
                                       u64 PC5, u64 PC4, u64 PC3, u64 PC2, u64 PC1, u64 PC0,
                                       float& r0, float& r1) {
    u64 tt = f2add(x, MAGICP);
    u64 nn = f2fma(MAGICP, NEG1P, tt);
    u64 ff = f2fma(nn, NEG1P, x);
    u64 p = f2fma(PC5, ff, PC4);
    p = f2fma(p, ff, PC3);
    p = f2fma(p, ff, PC2);
    p = f2fma(p, ff, PC1);
    p = f2fma(p, ff, PC0);
    float tl, th, pl_, ph_;
    f2up(tt, tl, th);
    f2up(p, pl_, ph_);
    int il = max(__float_as_int(tl) - 0x4B400000, -127);
    int ih = max(__float_as_int(th) - 0x4B400000, -127);
    r0 = __int_as_float(__float_as_int(pl_) + (il << 23));
    r1 = __int_as_float(__float_as_int(ph_) + (ih << 23));
}

// scalar exp2 (rescale path only)
__device__ __forceinline__ float exp2_fast(float x) {
    x = fmaxf(x, -126.f);
    float t = x + 12582912.f;
    int   i = __float_as_int(t) - 0x4B400000;
    float f = x - (t - 12582912.f);
    float p =            1.33336498e-3f;
    p = fmaf(p, f, 9.61793571e-3f);
    p = fmaf(p, f, 5.55041087e-2f);
    p = fmaf(p, f, 2.40226507e-1f);
    p = fmaf(p, f, 6.93147182e-1f);
    p = fmaf(p, f, 1.0f);
    return __int_as_float(__float_as_int(p) + (i << 23));
}

// ---------------------------------------------------------------------------
// Pre-pass: split fp32 -> fp16 hi/lo (elementwise)
// ---------------------------------------------------------------------------
__global__ void split_kernel(const float* __restrict__ src,
                             u16* __restrict__ hi, u16* __restrict__ lo, int n4) {
    int i = blockIdx.x * blockDim.x + threadIdx.x;
    if (i >= n4) return;
    float4 v = ((const float4*)src)[i];
    float a[4] = {v.x, v.y, v.z, v.w};
    ushort4 hv, lv;
    u16* hp = &hv.x;
    u16* lp = &lv.x;
#pragma unroll
    for (int j = 0; j < 4; j++) {
        __half h = __float2half(a[j]);
        float r = a[j] - __half2float(h);
        __half l = __float2half(r);
        hp[j] = __half_as_ushort(h);
        lp[j] = __half_as_ushort(l);
    }
    ((ushort4*)hi)[i] = hv;
    ((ushort4*)lo)[i] = lv;
}

// ---------------------------------------------------------------------------
// Pre-pass: transpose + split  W[K,N] fp32 -> Wt_hi/lo[N,K] fp16 (vectorized)
// ---------------------------------------------------------------------------
__global__ __launch_bounds__(256)
void transpose_split_kernel(const float* __restrict__ W,
                            u16* __restrict__ hi, u16* __restrict__ lo, int K, int N) {
    __shared__ float tile[32][33];
    int n0 = blockIdx.x * 32, k0 = blockIdx.y * 32;
    int t = threadIdx.x;
#pragma unroll
    for (int i = 0; i < 4; i++) {
        int idx = t + i * 256;
        int kk = idx >> 5, nn = idx & 31;
        tile[kk][nn] = W[(size_t)(k0 + kk) * N + n0 + nn];
    }
    __syncthreads();
    int n = t >> 3, kg = t & 7;
    ushort4 hv, lv;
    u16* hp = &hv.x;
    u16* lp = &lv.x;
#pragma unroll
    for (int j = 0; j < 4; j++) {
        float v = tile[kg * 4 + j][n];
        __half h = __float2half(v);
        float r = v - __half2float(h);
        __half l = __float2half(r);
        hp[j] = __half_as_ushort(h);
        lp[j] = __half_as_ushort(l);
    }
    size_t o = ((size_t)(n0 + n) * K + k0 + kg * 4) >> 2;
    ((ushort4*)hi)[o] = hv;
    ((ushort4*)lo)[o] = lv;
}

// ---------------------------------------------------------------------------
// sq-norm kernel: |row|^2 * ln2 (q and k), fp16 hi+lo reconstruction
// ---------------------------------------------------------------------------
__global__ __launch_bounds__(256)
void sqnorm_kernel() {
    const uint32_t* hi = blockIdx.y ? (const uint32_t*)g_khi : (const uint32_t*)g_qhi;
    const uint32_t* lo = blockIdx.y ? (const uint32_t*)g_klo : (const uint32_t*)g_qlo;
    float* out = blockIdx.y ? g_ksq : g_qsq;
    size_t gw = (size_t)blockIdx.x * 8 + (threadIdx.x >> 5);
    int lane = threadIdx.x & 31;
    uint32_t h = hi[gw * 32 + lane], l = lo[gw * 32 + lane];
    float h0, h1, l0v, l1v;
    unpack_f16x2(h, h0, h1);
    unpack_f16x2(l, l0v, l1v);
    float f0 = h0 + l0v, f1 = h1 + l1v;
    float s = fmaf(f0, f0, f1 * f1);
#pragma unroll
    for (int o = 16; o; o >>= 1) s += __shfl_xor_sync(0xffffffffu, s, o);
    if (lane == 0) out[gw] = s * LN2F;
}

// ---------------------------------------------------------------------------
// HMMA GEMM mainloop: 3-stage cp.async, 1 barrier/k-tile. NT = split terms.
// NT=3: AhBh+AhBl+AlBh.  NT=2: AhBh+AhBl (Al never loaded).
// ---------------------------------------------------------------------------
#define TILE64 (128 * 64)
#define STG64  (4 * TILE64)
#define GEMM_SMEM (3 * STG64)
#define NKT (KD / 32)

#define SWZ(r, c) ((uint32_t)((r) * 64 + ((((c) + ((r) >> 1)) & 3) << 4)))

template <int NT>
__device__ __forceinline__ void g2s_stage(uint32_t sdst,
                                          const u16* Ah, const u16* Al,
                                          const u16* Bh, const u16* Bl,
                                          int m0, int n0, int k0, int t) {
#pragma unroll
    for (int i = 0; i < 2; i++) {
        int idx = t + i * 256;
        int r = idx >> 2;
        int c = idx & 3;
        uint32_t soff = SWZ(r, c);
        size_t ga = (size_t)(m0 + r) * KD + k0 + c * 8;
        size_t gb = (size_t)(n0 + r) * KD + k0 + c * 8;
        CP16(sdst + soff,              (const char*)(Ah + ga));
        if (NT == 3)
            CP16(sdst + TILE64 + soff, (const char*)(Al + ga));
        CP16(sdst + 2 * TILE64 + soff, (const char*)(Bh + gb));
        CP16(sdst + 3 * TILE64 + soff, (const char*)(Bl + gb));
    }
}

template <int NT>
__device__ __forceinline__ void gemm_mainloop(
        uint32_t sb, const u16* Ah, const u16* Al,
        const u16* Bh, const u16* Bl,
        int m0, int n0, int t, float acc[4][4][4]) {
    const int lane = t & 31;
    const int w    = t >> 5;
    const int wm   = w & 1;
    const int wn   = w >> 1;
    const int g    = lane >> 3;

    uint32_t st0 = sb, st1 = sb + STG64, st2 = sb + 2 * STG64;

    g2s_stage<NT>(st0, Ah, Al, Bh, Bl, m0, n0, 0,  t); CP_COMMIT();
    g2s_stage<NT>(st1, Ah, Al, Bh, Bl, m0, n0, 32, t); CP_COMMIT();

    for (int kt = 0; kt < NKT; kt++) {
        if (kt == NKT - 1) { CP_WAIT(0); } else { CP_WAIT(1); }
        __syncthreads();
        if (kt + 2 < NKT) {
            g2s_stage<NT>(st2, Ah, Al, Bh, Bl, m0, n0, (kt + 2) * 32, t);
            CP_COMMIT();
        }

#pragma unroll
        for (int ks = 0; ks < 2; ks++) {
            uint32_t ah[4][4], al[4][4];
#pragma unroll
            for (int mi = 0; mi < 4; mi++) {
                int row = wm * 64 + mi * 16 + (lane & 15);
                int c   = ks * 2 + (lane >> 4);
                uint32_t ra = st0 + SWZ(row, c);
                ldsm_x4(ah[mi], ra);
                if (NT == 3) ldsm_x4(al[mi], ra + TILE64);
            }
            uint32_t bh[4][2], bl[4][2];
#pragma unroll
            for (int nb = 0; nb < 2; nb++) {
                int row = wn * 32 + nb * 16 + (g >> 1) * 8 + (lane & 7);
                int c   = ks * 2 + (g & 1);
                uint32_t rb = st0 + 2 * TILE64 + SWZ(row, c);
                ldsm_x4(&bh[2 * nb][0], rb);
                ldsm_x4(&bl[2 * nb][0], rb + TILE64);
            }
#pragma unroll
            for (int mi = 0; mi < 4; mi++)
#pragma unroll
                for (int ni = 0; ni < 4; ni++) mma16816(acc[mi][ni], ah[mi], bh[ni]);
#pragma unroll
            for (int mi = 0; mi < 4; mi++)
#pragma unroll
                for (int ni = 0; ni < 4; ni++) mma16816(acc[mi][ni], ah[mi], bl[ni]);
            if (NT == 3) {
#pragma unroll
                for (int mi = 0; mi < 4; mi++)
#pragma unroll
                    for (int ni = 0; ni < 4; ni++) mma16816(acc[mi][ni], al[mi], bh[ni]);
            }
        }
        uint32_t tmp = st0; st0 = st1; st1 = st2; st2 = tmp;
    }
}

// GEMM2: 2-term split, plain fp32 + bias epilogue (writes final output)
__global__ __launch_bounds__(256, 2)
void mma_gemm_kernel(const u16* __restrict__ Ah, const u16* __restrict__ Al,
                     const u16* __restrict__ Bh, const u16* __restrict__ Bl,
                     const float* __restrict__ bias,
                     float* __restrict__ C, int N) {
    extern __shared__ char smem[];
    const uint32_t sb = smem_u32(smem);
    const int t = threadIdx.x, lane = t & 31, w = t >> 5;
    const int wm = w & 1, wn = w >> 1;
    const int m0 = blockIdx.y * 128, n0 = blockIdx.x * 128;

    float acc[4][4][4];
#pragma unroll
    for (int mi = 0; mi < 4; mi++)
#pragma unroll
        for (int ni = 0; ni < 4; ni++)
#pragma unroll
            for (int r = 0; r < 4; r++) acc[mi][ni][r] = 0.f;

    gemm_mainloop<2>(sb, Ah, Al, Bh, Bl, m0, n0, t, acc);

#pragma unroll
    for (int mi = 0; mi < 4; mi++) {
        int row = m0 + wm * 64 + mi * 16 + (lane >> 2);
#pragma unroll
        for (int ni = 0; ni < 4; ni++) {
            int col = n0 + wn * 32 + ni * 8 + (lane & 3) * 2;
            float b0 = bias[col], b1 = bias[col + 1];
            float2 v0 = {acc[mi][ni][0] + b0, acc[mi][ni][1] + b1};
            float2 v1 = {acc[mi][ni][2] + b0, acc[mi][ni][3] + b1};
            *(float2*)&C[(size_t)row * N + col]       = v0;
            *(float2*)&C[(size_t)(row + 8) * N + col] = v1;
        }
    }
}

// GEMM1: 2-term split, fused epilogue -> per-head fp16 hi/lo q/k/v
__global__ __launch_bounds__(256, 2)
void mma_gemm_qkv_kernel(const u16* __restrict__ Ah, const u16* __restrict__ Al,
                         const u16* __restrict__ Bh, const u16* __restrict__ Bl,
                         const float* __restrict__ bias) {
    extern __shared__ char smem[];
    const uint32_t sb = smem_u32(smem);
    const int t = threadIdx.x, lane = t & 31, w = t >> 5;
    const int wm = w & 1, wn = w >> 1;
    const int m0 = blockIdx.y * 128, n0 = blockIdx.x * 128;

    float acc[4][4][4];
#pragma unroll
    for (int mi = 0; mi < 4; mi++)
#pragma unroll
        for (int ni = 0; ni < 4; ni++)
#pragma unroll
            for (int r = 0; r < 4; r++) acc[mi][ni][r] = 0.f;

    gemm_mainloop<2>(sb, Ah, Al, Bh, Bl, m0, n0, t, acc);

    const int sec = n0 >> 10;     // 0=q, 1=k, 2=v
    uint32_t* ph = sec == 0 ? (uint32_t*)g_qhi : sec == 1 ? (uint32_t*)g_khi : (uint32_t*)g_vhi;
    uint32_t* pl = sec == 0 ? (uint32_t*)g_qlo : sec == 1 ? (uint32_t*)g_klo : (uint32_t*)g_vlo;

#pragma unroll
    for (int mi = 0; mi < 4; mi++) {
        int row = m0 + wm * 64 + mi * 16 + (lane >> 2);
        int b   = row >> 11, tok = row & (TSEQ - 1);
#pragma unroll
        for (int ni = 0; ni < 4; ni++) {
            int col  = n0 + wn * 32 + ni * 8 + (lane & 3) * 2;
            int head = (col >> 6) & (NHEAD - 1);
            int d    = col & 63;
            size_t base = ((size_t)(b * NHEAD + head) * TSEQ) * 32 + (d >> 1);
            float b0 = bias[col], b1 = bias[col + 1];
#pragma unroll
            for (int r2 = 0; r2 < 2; r2++) {
                float v0 = acc[mi][ni][2 * r2]     + b0;
                float v1 = acc[mi][ni][2 * r2 + 1] + b1;
                uint32_t lv;
                uint32_t hv = split_pair_f16(v0, v1, lv);
                size_t idx = base + (size_t)(tok + r2 * 8) * 32;
                ph[idx] = hv;
                pl[idx] = lv;
            }
        }
    }
}

// ---------------------------------------------------------------------------
// FlashAttention-style Yat attention: QK 3-term, PV 2-term, fp16 splits.
// (round-16 winner, unchanged)
// ---------------------------------------------------------------------------
#define AROWB 144
#define QLOFF  18432
#define SBASE  36864
#define KLOFF  9216
#define VHOFF  18432
#define VLOFF  27648
#define KSQOFF 36864
#define ASTG   37120
#define ATT_SMEM (SBASE + 2 * ASTG)

__device__ __forceinline__ void load_kv(uint32_t dst,
                                        const char* kh, const char* kl,
                                        const char* vh, const char* vl,
                                        const char* ksq, int kt, int t) {
#pragma unroll
    for (int i = 0; i < 2; i++) {
        int idx = t + i * 256;
        int rr = idx >> 3, cc = idx & 7;
        uint32_t off = (uint32_t)(rr * AROWB + cc * 16);
        size_t gbyte = ((size_t)(kt * 64 + rr) * HDIM + cc * 8) * 2;
        CP16(dst + off,         kh + gbyte);
        CP16(dst + KLOFF + off, kl + gbyte);
        CP16(dst + VHOFF + off, vh + gbyte);
        CP16(dst + VLOFF + off, vl + gbyte);
    }
    if (t < 16) CP16(dst + KSQOFF + t * 16, ksq + (size_t)kt * 64 * 4 + t * 16);
}

__global__ __launch_bounds__(256, 2)
void yat_attn_mma() {
    extern __shared__ char smem[];
    const uint32_t sb = smem_u32(smem);

    const int t = threadIdx.x, lane = t & 31, w = t >> 5;
    const int h = blockIdx.y, b = blockIdx.z;
    const int qt = gridDim.x - 1 - blockIdx.x;
    const int q0 = qt * 128;
    const int bh = b * NHEAD + h;
    const size_t hb = (size_t)bh * TSEQ * HDIM;

    const char* pQh = (const char*)(g_qhi + hb);
    const char* pQl = (const char*)(g_qlo + hb);
    const char* pKh = (const char*)(g_khi + hb);
    const char* pKl = (const char*)(g_klo + hb);
    const char* pVh = (const char*)(g_vhi + hb);
    const char* pVl = (const char*)(g_vlo + hb);
    const char* pKs = (const char*)(g_ksq + (size_t)bh * TSEQ);

    const int nkt = 2 * qt + 2;

#pragma unroll
    for (int i = 0; i < 4; i++) {
        int idx = t + i * 256;
        int r = idx >> 3, c = idx & 7;
        uint32_t d = sb + (uint32_t)(r * AROWB + c * 16);
        size_t gbyte = ((size_t)(q0 + r) * HDIM + c * 8) * 2;
        CP16(d,          pQh + gbyte);
        CP16(d + QLOFF,  pQl + gbyte);
    }
    CP_COMMIT();
    load_kv(sb + SBASE,        pKh, pKl, pVh, pVl, pKs, 0, t); CP_COMMIT();
    load_kv(sb + SBASE + ASTG, pKh, pKl, pVh, pVl, pKs, 1, t); CP_COMMIT();

    const int rl  = lane >> 2;
    const int rg0 = q0 + w * 16 + rl;
    const int rg1 = rg0 + 8;
    const float qa0 = g_qsq[(size_t)bh * TSEQ + rg0] + EPS * LN2F;
    const float qa1 = g_qsq[(size_t)bh * TSEQ + rg1] + EPS * LN2F;

    const u64 MAGICP = f2bcast(12582912.f);
    const u64 NEG1P  = f2bcast(-1.f);
    const u64 TWOP   = f2bcast(2.f);
    const u64 C2P    = f2bcast(-2.f * LN2F);
    const u64 PC5 = f2bcast(1.33336498e-3f);
    const u64 PC4 = f2bcast(9.61793571e-3f);
    const u64 PC3 = f2bcast(5.55041087e-2f);
    const u64 PC2 = f2bcast(2.40226507e-1f);
    const u64 PC1 = f2bcast(6.93147182e-1f);
    const u64 PC0 = f2bcast(1.0f);
    const u64 QA0P = f2bcast(qa0);
    const u64 QA1P = f2bcast(qa1);

    float O[8][4];
#pragma unroll
    for (int dt = 0; dt < 8; dt++)
#pragma unroll
        for (int r = 0; r < 4; r++) O[dt][r] = 0.f;
    float m0 = -1e30f, m1 = -1e30f, l0 = 0.f, l1 = 0.f;

    for (int i = 0; i < nkt; i++) {
        if (i == nkt - 1) { CP_WAIT(0); } else { CP_WAIT(1); }
        __syncthreads();

        const uint32_t kb = sb + SBASE + (uint32_t)(i & 1) * ASTG;
        const char* kbp = smem + SBASE + (size_t)(i & 1) * ASTG;
        const float* ksqp = (const float*)(kbp + KSQOFF);
        const int k0 = i * 64;
        const bool need_mask = (k0 + 63 > q0 + w * 16);

        // ---- S = Q K^T (3-term fp16 split) ----
        float S[8][4];
#pragma unroll
        for (int nt = 0; nt < 8; nt++)
#pragma unroll
            for (int r = 0; r < 4; r++) S[nt][r] = 0.f;

        const int g = lane >> 3;
#pragma unroll
        for (int ks = 0; ks < 4; ks++) {
            uint32_t ah[4], al[4];
            uint32_t qaddr = sb + (uint32_t)((w * 16 + (lane & 15)) * AROWB
                                             + ks * 32 + (lane >> 4) * 16);
            ldsm_x4(ah, qaddr);
            ldsm_x4(al, qaddr + QLOFF);
#pragma unroll
            for (int nbp = 0; nbp < 4; nbp += 2) {
                uint32_t bhA[4], blA[4], bhB[4], blB[4];
                uint32_t kaddrA = kb + (uint32_t)((nbp * 16 + (g >> 1) * 8 + (lane & 7)) * AROWB
                                                  + ks * 32 + (g & 1) * 16);
                uint32_t kaddrB = kaddrA + 16 * AROWB;
                ldsm_x4(bhA, kaddrA);
                ldsm_x4(blA, kaddrA + KLOFF);
                ldsm_x4(bhB, kaddrB);
                ldsm_x4(blB, kaddrB + KLOFF);
                mma16816(S[2 * nbp],     ah, bhA);
                mma16816(S[2 * nbp + 1], ah, bhA + 2);
                mma16816(S[2 * nbp + 2], ah, bhB);
                mma16816(S[2 * nbp + 3], ah, bhB + 2);
                mma16816(S[2 * nbp],     al, bhA);
                mma16816(S[2 * nbp + 1], al, bhA + 2);
                mma16816(S[2 * nbp + 2], al, bhB);
                mma16816(S[2 * nbp + 3], al, bhB + 2);
                mma16816(S[2 * nbp],     ah, blA);
                mma16816(S[2 * nbp + 1], ah, blA + 2);
                mma16816(S[2 * nbp + 2], ah, blB);
                mma16816(S[2 * nbp + 3], ah, blB + 2);
            }
        }

        // ---- scores + mask + max (packed f32x2) ----
        u64 SP[8][2];
        float mx0 = -1e30f, mx1 = -1e30f;
#pragma unroll
        for (int nt = 0; nt < 8; nt++) {
            int cb = nt * 8 + 2 * (lane & 3);
            float2 ksv = *(const float2*)&ksqp[cb];
            u64 kpp = f2pk(ksv.x, ksv.y);
            u64 d0 = f2pk(S[nt][0], S[nt][1]);
            u64 d1 = f2pk(S[nt][2], S[nt][3]);
            u64 den0 = f2fma(C2P, d0, f2add(QA0P, kpp));
            u64 den1 = f2fma(C2P, d1, f2add(QA1P, kpp));
            u64 sl0 = f2mul(f2mul(d0, d0), f2rcp(den0, TWOP, NEG1P));
            u64 sl1 = f2mul(f2mul(d1, d1), f2rcp(den1, TWOP, NEG1P));
            float a0, a1, b0, b1;
            f2up(sl0, a0, a1);
            f2up(sl1, b0, b1);
            if (need_mask) {
                int cg = k0 + cb;
                if (cg > rg0)     a0 = -1e30f;
                if (cg + 1 > rg0) a1 = -1e30f;
                if (cg > rg1)     b0 = -1e30f;
                if (cg + 1 > rg1) b1 = -1e30f;
            }
            mx0 = fmaxf(mx0, fmaxf(a0, a1));
            mx1 = fmaxf(mx1, fmaxf(b0, b1));
            SP[nt][0] = f2pk(a0, a1);
            SP[nt][1] = f2pk(b0, b1);
        }
        mx0 = fmaxf(mx0, __shfl_xor_sync(0xffffffffu, mx0, 1));
        mx0 = fmaxf(mx0, __shfl_xor_sync(0xffffffffu, mx0, 2));
        mx1 = fmaxf(mx1, __shfl_xor_sync(0xffffffffu, mx1, 1));
        mx1 = fmaxf(mx1, __shfl_xor_sync(0xffffffffu, mx1, 2));
        float mn0 = fmaxf(m0, mx0), mn1 = fmaxf(m1, mx1);
        float sc0 = exp2_fast(m0 - mn0), sc1 = exp2_fast(m1 - mn1);
        m0 = mn0; m1 = mn1;
        if (__any_sync(0xffffffffu, (sc0 != 1.f) || (sc1 != 1.f))) {
            l0 *= sc0; l1 *= sc1;
#pragma unroll
            for (int dt = 0; dt < 8; dt++) {
                O[dt][0] *= sc0; O[dt][1] *= sc0;
                O[dt][2] *= sc1; O[dt][3] *= sc1;
            }
        }

        // ---- p = exp2(sl - m) (packed), fp16 hi only ----
        const u64 NM0 = f2bcast(-mn0);
        const u64 NM1 = f2bcast(-mn1);
        uint32_t pH[8][2];
#pragma unroll
        for (int nt = 0; nt < 8; nt++) {
            float p0, p1, p2, p3;
            f2exp2(f2add(SP[nt][0], NM0), MAGICP, NEG1P, PC5, PC4, PC3, PC2, PC1, PC0, p0, p1);
            f2exp2(f2add(SP[nt][1], NM1), MAGICP, NEG1P, PC5, PC4, PC3, PC2, PC1, PC0, p2, p3);
            l0 += p0 + p1;
            l1 += p2 + p3;
            pH[nt][0] = pack_f16x2(p1, p0);
            pH[nt][1] = pack_f16x2(p3, p2);
        }

        // ---- O += P (Vh + Vl), 2-term ----
        const int vrow = (lane & 7) + ((lane >> 3) & 1) * 8;
        const int vcol = ((lane >> 4) & 1) * 16;
#pragma unroll
        for (int kc = 0; kc < 4; kc++) {
            uint32_t aH[4] = {pH[2 * kc][0], pH[2 * kc][1], pH[2 * kc + 1][0], pH[2 * kc + 1][1]};
#pragma unroll
            for (int dpp = 0; dpp < 4; dpp += 2) {
                uint32_t vaddrA = kb + VHOFF
                                + (uint32_t)((kc * 16 + vrow) * AROWB + dpp * 32 + vcol);
                uint32_t vaddrB = vaddrA + 32;
                uint32_t vhA[4], vlA[4], vhB[4], vlB[4];
                ldsm_x4t(vhA, vaddrA);
                ldsm_x4t(vlA, vaddrA + KLOFF);
                ldsm_x4t(vhB, vaddrB);
                ldsm_x4t(vlB, vaddrB + KLOFF);
                mma16816(O[2 * dpp],     aH, vhA);
                mma16816(O[2 * dpp + 1], aH, vhA + 2);
                mma16816(O[2 * dpp + 2], aH, vhB);
                mma16816(O[2 * dpp + 3], aH, vhB + 2);
                mma16816(O[2 * dpp],     aH, vlA);
                mma16816(O[2 * dpp + 1], aH, vlA + 2);
                mma16816(O[2 * dpp + 2], aH, vlB);
                mma16816(O[2 * dpp + 3], aH, vlB + 2);
            }
        }

        __syncthreads();
        if (i + 2 < nkt) {
            load_kv(kb, pKh, pKl, pVh, pVl, pKs, i + 2, t);
            CP_COMMIT();
        }
    }

    // ---- finalize: normalize, fp16 hi/lo split, store ----
    l0 += __shfl_xor_sync(0xffffffffu, l0, 1);
    l0 += __shfl_xor_sync(0xffffffffu, l0, 2);
    l1 += __shfl_xor_sync(0xffffffffu, l1, 1);
    l1 += __shfl_xor_sync(0xffffffffu, l1, 2);
    float i0 = __fdividef(1.f, l0);
    float i1 = __fdividef(1.f, l1);

    uint32_t* oh = (uint32_t*)g_atthi;
    uint32_t* ol = (uint32_t*)g_attlo;
    size_t base0 = (((size_t)(b * TSEQ + rg0)) * CDIM + h * HDIM + 2 * (lane & 3)) >> 1;
    size_t base1 = (((size_t)(b * TSEQ + rg1)) * CDIM + h * HDIM + 2 * (lane & 3)) >> 1;
#pragma unroll
    for (int dt = 0; dt < 8; dt++) {
        float v0 = O[dt][0] * i0, v1 = O[dt][1] * i0;
        float v2 = O[dt][2] * i1, v3 = O[dt][3] * i1;
        uint32_t lv0, lv1;
        uint32_t hv0 = split_pair_f16(v0, v1, lv0);
        uint32_t hv1 = split_pair_f16(v2, v3, lv1);
        oh[base0 + dt * 4] = hv0;
        ol[base0 + dt * 4] = lv0;
        oh[base1 + dt * 4] = hv1;
        ol[base1 + dt * 4] = lv1;
    }
}

// ---------------------------------------------------------------------------
// Launch
// ---------------------------------------------------------------------------
extern "C" void kernel_launch(void* const* d_in, const int* in_sizes, int n_in,
                              void* d_out, int out_size) {
    const float* x     = (const float*)d_in[0];
    const float* w_qkv = (const float*)d_in[1];
    const float* b_qkv = (const float*)d_in[2];
    const float* w_out = (const float*)d_in[3];
    const float* b_out = (const float*)d_in[4];
    float* out = (float*)d_out;

    void *p_xhi, *p_xlo, *p_wqh, *p_wql, *p_woh, *p_wol, *p_ahi, *p_alo;
    cudaGetSymbolAddress(&p_xhi, g_xhi);
    cudaGetSymbolAddress(&p_xlo, g_xlo);
    cudaGetSymbolAddress(&p_wqh, g_wqkvT_hi);
    cudaGetSymbolAddress(&p_wql, g_wqkvT_lo);
    cudaGetSymbolAddress(&p_woh, g_woT_hi);
    cudaGetSymbolAddress(&p_wol, g_woT_lo);
    cudaGetSymbolAddress(&p_ahi, g_atthi);
    cudaGetSymbolAddress(&p_alo, g_attlo);

    static bool attr_done = false;
    if (!attr_done) {
        cudaFuncSetAttribute(mma_gemm_kernel,
                             cudaFuncAttributeMaxDynamicSharedMemorySize, GEMM_SMEM);
        cudaFuncSetAttribute(mma_gemm_qkv_kernel,
                             cudaFuncAttributeMaxDynamicSharedMemorySize, GEMM_SMEM);
        cudaFuncSetAttribute(yat_attn_mma,
                             cudaFuncAttributeMaxDynamicSharedMemorySize, ATT_SMEM);
        attr_done = true;
    }

    // 0) split x, transpose+split weights (fp16)
    {
        int n4 = MTOT * KD / 4;
        split_kernel<<<(n4 + 255) / 256, 256>>>(x, (u16*)p_xhi, (u16*)p_xlo, n4);
        dim3 g1(N1 / 32, KD / 32);
        transpose_split_kernel<<<g1, 256>>>(w_qkv, (u16*)p_wqh, (u16*)p_wql, KD, N1);
        dim3 g2(CDIM / 32, KD / 32);
        transpose_split_kernel<<<g2, 256>>>(w_out, (u16*)p_woh, (u16*)p_wol, KD, CDIM);
    }

    // 1) QKV projection (2-term), fused epilogue -> per-head fp16 splits
    {
        dim3 grid(N1 / 128, MTOT / 128);
        mma_gemm_qkv_kernel<<<grid, 256, GEMM_SMEM>>>(
            (const u16*)p_xhi, (const u16*)p_xlo,
            (const u16*)p_wqh, (const u16*)p_wql, b_qkv);
    }

    // 2) sq-norms (ln2-scaled) + HMMA flash attention
    {
        dim3 gs((unsigned)(BHT / 8), 2);
        sqnorm_kernel<<<gs, 256>>>();
        dim3 grid(TSEQ / 128, NHEAD, BSZ);
        yat_attn_mma<<<grid, 256, ATT_SMEM>>>();
    }

    // 3) output projection (2-term)
    {
        dim3 grid(CDIM / 128, MTOT / 128);
        mma_gemm_kernel<<<grid, 256, GEMM_SMEM>>>(
            (const u16*)p_ahi, (const u16*)p_alo,
            (const u16*)p_woh, (const u16*)p_wol,
            b_out, out, CDIM);
    }
}